// round 8
// baseline (speedup 1.0000x reference)
#include <cuda_runtime.h>
#include <cuda_bf16.h>
#include <math.h>
#include <stdint.h>

#define N      8192
#define D      256
#define NC     64
#define KNN5   5
#define TI     128
#define KC     64           // bf16 per smem stage (128 B/row)
#define NSTG   4            // K=256 / 64
#define NBI    (N/TI)       // 64 block-rows
#define NCAND  8            // approx candidates kept per tile
#define CAND   (NBI*NCAND)  // 512 candidate slots per row
#define NB_IT  148
#define IT_THREADS 512
#define IT_WARPS   16
#define ROWS_MAX   4
#define MAXIT  100
#define LAM    1.0f

// ---------------- scratch ----------------------------------------------------
__device__ __nv_bfloat16 g_H[(size_t)N * D];    // bf16(normalized feats)
__device__ float g_F[(size_t)N * D];            // fp32 normalized feats
__device__ float g_unary[N * NC];
__device__ float g_Ybuf[2][N * NC];
__device__ float g_candV[(size_t)N * CAND];     // [row][slot]
__device__ int   g_candI[(size_t)N * CAND];
__device__ int   g_nbr[N * KNN5];
__device__ uint64_t g_slotE[(size_t)MAXIT * NB_IT];
__device__ uint64_t g_bcastE[MAXIT];

// ---------------- PTX helpers ------------------------------------------------
__device__ __forceinline__ uint32_t smem_u32(const void* p) {
    uint32_t a;
    asm("{ .reg .u64 t; cvta.to.shared.u64 t, %1; cvt.u32.u64 %0, t; }" : "=r"(a) : "l"(p));
    return a;
}
#define SWZ128(o) ((o) ^ (((o) >> 3) & 0x70))
#define CP_ASYNC16(dst, src) \
    asm volatile("cp.async.cg.shared.global [%0], [%1], 16;" :: "r"(dst), "l"(src) : "memory")
#define CP_COMMIT() asm volatile("cp.async.commit_group;" ::: "memory")
#define CP_WAIT(n)  asm volatile("cp.async.wait_group %0;" :: "n"(n) : "memory")
#define LDSM_X4(r0,r1,r2,r3, a) \
    asm volatile("ldmatrix.sync.aligned.m8n8.x4.shared.b16 {%0,%1,%2,%3}, [%4];" \
        : "=r"(r0),"=r"(r1),"=r"(r2),"=r"(r3) : "r"(a))
#define LDSM_X2(r0,r1, a) \
    asm volatile("ldmatrix.sync.aligned.m8n8.x2.shared.b16 {%0,%1}, [%2];" \
        : "=r"(r0),"=r"(r1) : "r"(a))
#define MMA16816(d, a, b) \
    asm volatile("mma.sync.aligned.m16n8k16.row.col.f32.bf16.bf16.f32 " \
        "{%0,%1,%2,%3}, {%4,%5,%6,%7}, {%8,%9}, {%0,%1,%2,%3};" \
        : "+f"((d)[0]),"+f"((d)[1]),"+f"((d)[2]),"+f"((d)[3]) \
        : "r"((a)[0]),"r"((a)[1]),"r"((a)[2]),"r"((a)[3]), "r"((b)[0]),"r"((b)[1]))

__device__ __forceinline__ void st_rel64(uint64_t* p, uint64_t v) {
    asm volatile("st.release.gpu.global.b64 [%0], %1;" :: "l"(p), "l"(v) : "memory");
}
__device__ __forceinline__ uint64_t ld_acq64(const uint64_t* p) {
    uint64_t v;
    asm volatile("ld.acquire.gpu.global.b64 %0, [%1];" : "=l"(v) : "l"(p) : "memory");
    return v;
}

// ---------------- top-K insert (lexicographic: value desc, index asc) --------
template <int K>
__device__ __forceinline__ void topk_insert(float v, int j, float* bv, int* bi) {
    if (v > bv[K-1] || (v == bv[K-1] && j < bi[K-1])) {
        bv[K-1] = v; bi[K-1] = j;
#pragma unroll
        for (int s = K-1; s > 0; --s) {
            if (bv[s] > bv[s-1] || (bv[s] == bv[s-1] && bi[s] < bi[s-1])) {
                float tv = bv[s]; bv[s] = bv[s-1]; bv[s-1] = tv;
                int   tj = bi[s]; bi[s] = bi[s-1]; bi[s-1] = tj;
            }
        }
    }
}

// ---------------- reset sync slots (graph-replay safe) -----------------------
__global__ void k_reset() {
    int i = blockIdx.x * 256 + threadIdx.x;
    if (i < MAXIT * NB_IT) g_slotE[i] = 0ull;
    if (i < MAXIT) g_bcastE[i] = 0ull;
}

// ---------------- prep: unary + Y0 ------------------------------------------
__global__ void k_prep_unary(const float* __restrict__ scores) {
    int wib = threadIdx.x >> 5, lane = threadIdx.x & 31;
    int r = blockIdx.x * 8 + wib;
    const float* s = scores + (size_t)r * NC;
    float u0 = -logf(s[lane]      + 1e-10f);
    float u1 = -logf(s[lane + 32] + 1e-10f);
    g_unary[r * NC + lane]      = u0;
    g_unary[r * NC + 32 + lane] = u1;
    float x0 = -u0, x1 = -u1;
    float m = fmaxf(x0, x1);
#pragma unroll
    for (int o = 16; o > 0; o >>= 1) m = fmaxf(m, __shfl_xor_sync(0xffffffffu, m, o));
    float e0 = __expf(x0 - m), e1 = __expf(x1 - m);
    float t = e0 + e1;
#pragma unroll
    for (int o = 16; o > 0; o >>= 1) t += __shfl_xor_sync(0xffffffffu, t, o);
    float inv = 1.0f / t;
    g_Ybuf[0][r * NC + lane]      = e0 * inv;
    g_Ybuf[0][r * NC + 32 + lane] = e1 * inv;
}

// ---------------- prep: normalize -> fp32 + bf16 -----------------------------
__global__ void k_prep_feats(const float* __restrict__ feats) {
    __shared__ float red[8];
    __shared__ float nrmsh;
    int r = blockIdx.x, k = threadIdx.x;
    int lane = k & 31, w = k >> 5;
    float v = feats[(size_t)r * D + k];
    float s = v * v;
#pragma unroll
    for (int o = 16; o > 0; o >>= 1) s += __shfl_xor_sync(0xffffffffu, s, o);
    if (lane == 0) red[w] = s;
    __syncthreads();
    if (k == 0) {
        float t = 0.f;
#pragma unroll
        for (int i = 0; i < 8; ++i) t += red[i];
        nrmsh = sqrtf(t);
    }
    __syncthreads();
    float f = v / fmaxf(nrmsh, 1e-12f);
    g_F[(size_t)r * D + k] = f;
    g_H[(size_t)r * D + k] = __float2bfloat16(f);
}

// ---------------- bf16 Gram (K=256), upper-triangle, fused dual top-8 --------
// grid 2080 x 256; dynamic smem = 3 stages x 32KB = 96 KB (2 CTAs/SM)
__global__ void __launch_bounds__(256, 2) k_gram_mma() {
    extern __shared__ char smem[];
    float* Cs = (float*)smem;                 // [64][129] epilogue overlay
    const uint32_t sb = smem_u32(smem);
    const int tid = threadIdx.x;
    const int lane = tid & 31, warp = tid >> 5;
    const int wm = warp >> 2, wn = warp & 3;

    int bi = 0, rem = blockIdx.x;
    while (rem >= NBI - bi) { rem -= NBI - bi; ++bi; }
    const int bj = bi + rem;
    const int ib = bi * TI, jb = bj * TI;

    float acc[4][4][4];
#pragma unroll
    for (int mf = 0; mf < 4; ++mf)
#pragma unroll
        for (int nf = 0; nf < 4; ++nf)
#pragma unroll
            for (int q = 0; q < 4; ++q) acc[mf][nf][q] = 0.f;

    const char* gH = (const char*)g_H;

#define LOAD_STAGE(sidx) do {                                                   \
        int _s = (sidx); uint32_t _b = (uint32_t)((sidx) % 3) * 32768u;         \
        _Pragma("unroll")                                                       \
        for (int t = 0; t < 4; ++t) {                                           \
            int e = tid + t * 256;                                              \
            int row = e >> 3, ch = e & 7;                                       \
            uint32_t off = SWZ128((uint32_t)(row * 128 + ch * 16));             \
            CP_ASYNC16(sb + _b + off,                                           \
                gH + ((size_t)(ib + row) * D + (size_t)_s * KC) * 2 + ch * 16); \
            CP_ASYNC16(sb + _b + 16384u + off,                                  \
                gH + ((size_t)(jb + row) * D + (size_t)_s * KC) * 2 + ch * 16); \
        }                                                                       \
        CP_COMMIT();                                                            \
    } while (0)

    LOAD_STAGE(0);
    LOAD_STAGE(1);

    for (int s = 0; s < NSTG; ++s) {
        // wait own group s, THEN barrier => all threads' group-s bytes visible.
        if (s == NSTG - 1) { CP_WAIT(0); } else { CP_WAIT(1); }
        __syncthreads();
        // prefetch s+2 into buffer (s+2)%3 == (s-1)%3; safe: barrier above is
        // after every thread's compute of stage s-1.
        if (s + 2 < NSTG) LOAD_STAGE(s + 2);

        const uint32_t aS = sb + (uint32_t)(s % 3) * 32768u;
        const uint32_t bS = aS + 16384u;
#pragma unroll
        for (int kk = 0; kk < 4; ++kk) {
            uint32_t a[4][4], b[4][2];
#pragma unroll
            for (int mf = 0; mf < 4; ++mf) {
                int row = wm * 64 + mf * 16 + (lane & 15);
                uint32_t kb = kk * 32 + ((lane >> 4) << 4);
                LDSM_X4(a[mf][0], a[mf][1], a[mf][2], a[mf][3], aS + SWZ128((uint32_t)(row * 128) + kb));
            }
#pragma unroll
            for (int nf = 0; nf < 4; ++nf) {
                int nrow = wn * 32 + nf * 8 + (lane & 7);
                uint32_t kb = kk * 32 + (((lane >> 3) & 1) << 4);
                LDSM_X2(b[nf][0], b[nf][1], bS + SWZ128((uint32_t)(nrow * 128) + kb));
            }
#pragma unroll
            for (int mf = 0; mf < 4; ++mf)
#pragma unroll
                for (int nf = 0; nf < 4; ++nf)
                    MMA16816(acc[mf][nf], a[mf], b[nf]);
        }
    }

    // epilogue: two 64x128 halves through smem; row top-8 (i side), col top-8 (j side)
    float bvC[NCAND]; int biC[NCAND];
#pragma unroll
    for (int q = 0; q < NCAND; ++q) { bvC[q] = -__int_as_float(0x7f800000); biC[q] = 0x7fffffff; }

#pragma unroll
    for (int h = 0; h < 2; ++h) {
        __syncthreads();
        if (wm == h) {
#pragma unroll
            for (int mf = 0; mf < 4; ++mf)
#pragma unroll
                for (int nf = 0; nf < 4; ++nf) {
                    int r0 = mf * 16 + (lane >> 2);
                    int c0 = wn * 32 + nf * 8 + 2 * (lane & 3);
                    Cs[r0 * 129 + c0]           = acc[mf][nf][0];
                    Cs[r0 * 129 + c0 + 1]       = acc[mf][nf][1];
                    Cs[(r0 + 8) * 129 + c0]     = acc[mf][nf][2];
                    Cs[(r0 + 8) * 129 + c0 + 1] = acc[mf][nf][3];
                }
        }
        __syncthreads();
        if (tid < 64) {                        // i-side: row scan, slot group bj
            int gi = ib + h * 64 + tid;
            float bv[NCAND]; int bx[NCAND];
#pragma unroll
            for (int q = 0; q < NCAND; ++q) { bv[q] = -__int_as_float(0x7f800000); bx[q] = 0x7fffffff; }
            for (int c = 0; c < TI; ++c) {
                int gj = jb + c;
                if (gj != gi) topk_insert<NCAND>(Cs[tid * 129 + c], gj, bv, bx);
            }
#pragma unroll
            for (int q = 0; q < NCAND; ++q) {
                g_candV[(size_t)gi * CAND + bj * NCAND + q] = bv[q];
                g_candI[(size_t)gi * CAND + bj * NCAND + q] = bx[q];
            }
        }
        if (bi != bj && tid < 128) {           // j-side: col scan, slot group bi
            for (int r = 0; r < 64; ++r)
                topk_insert<NCAND>(Cs[r * 129 + tid], ib + h * 64 + r, bvC, biC);
        }
    }
    if (bi != bj && tid < 128) {
        int gj = jb + tid;
#pragma unroll
        for (int q = 0; q < NCAND; ++q) {
            g_candV[(size_t)gj * CAND + bi * NCAND + q] = bvC[q];
            g_candI[(size_t)gj * CAND + bi * NCAND + q] = biC[q];
        }
    }
#undef LOAD_STAGE
}

// ---------------- merge + exact fp32 rescore -> final 5-NN -------------------
// warp per row; 1024 blocks x 256 threads
__global__ void __launch_bounds__(256) k_nn() {
    const int warp = threadIdx.x >> 5, lane = threadIdx.x & 31;
    const int r = blockIdx.x * 8 + warp;

    // lane-local top-8 over 16 coalesced slots
    float bv[NCAND]; int bx[NCAND];
#pragma unroll
    for (int q = 0; q < NCAND; ++q) { bv[q] = -__int_as_float(0x7f800000); bx[q] = 0x7fffffff; }
    const size_t base = (size_t)r * CAND;
#pragma unroll
    for (int k = 0; k < CAND / 32; ++k) {
        int slot = lane + 32 * k;
        topk_insert<NCAND>(g_candV[base + slot], g_candI[base + slot], bv, bx);
    }
    // butterfly merge (all lanes converge to identical top-8)
#pragma unroll
    for (int off = 16; off > 0; off >>= 1) {
        float tv[NCAND]; int ti[NCAND];
#pragma unroll
        for (int q = 0; q < NCAND; ++q) {
            tv[q] = __shfl_xor_sync(0xffffffffu, bv[q], off);
            ti[q] = __shfl_xor_sync(0xffffffffu, bx[q], off);
        }
#pragma unroll
        for (int q = 0; q < NCAND; ++q) topk_insert<NCAND>(tv[q], ti[q], bv, bx);
    }

    // exact fp32 rescore of the 8 finalists
    float fr[8];
#pragma unroll
    for (int k = 0; k < 8; ++k) fr[k] = g_F[(size_t)r * D + lane + 32 * k];
    float dots[NCAND];
#pragma unroll
    for (int q = 0; q < NCAND; ++q) {
        const float* fc = g_F + (size_t)bx[q] * D;
        float s = 0.f;
#pragma unroll
        for (int k = 0; k < 8; ++k) s = fmaf(fr[k], fc[lane + 32 * k], s);
#pragma unroll
        for (int o = 16; o > 0; o >>= 1) s += __shfl_xor_sync(0xffffffffu, s, o);
        dots[q] = s;
    }
    // top-5 by exact (dot desc, idx asc)
    float b5[KNN5]; int i5[KNN5];
#pragma unroll
    for (int q = 0; q < KNN5; ++q) { b5[q] = -__int_as_float(0x7f800000); i5[q] = 0x7fffffff; }
#pragma unroll
    for (int q = 0; q < NCAND; ++q) topk_insert<KNN5>(dots[q], bx[q], b5, i5);
    if (lane < KNN5) g_nbr[r * KNN5 + lane] = i5[lane] < N ? i5[lane] : 0;
}

// ---------------- persistent mean-field iteration (flag-based global sync) ---
__global__ void __launch_bounds__(IT_THREADS) k_iterate(float* __restrict__ dout) {
    __shared__ float sE[IT_WARPS];
    __shared__ float sEarr[NB_IT];
    __shared__ float sEbc;
    const int tid  = threadIdx.x;
    const int lane = tid & 31, wib = tid >> 5;
    const int warpG = blockIdx.x * IT_WARPS + wib;
    const int nW = NB_IT * IT_WARPS;

    int nr = 0, rows[ROWS_MAX];
    float u0[ROWS_MAX], u1[ROWS_MAX];
    int   nb[ROWS_MAX][KNN5];
#pragma unroll
    for (int k = 0; k < ROWS_MAX; ++k) {
        rows[k] = 0; u0[k] = 0.f; u1[k] = 0.f;
#pragma unroll
        for (int n = 0; n < KNN5; ++n) nb[k][n] = 0;
    }
    for (int rr = warpG; rr < N; rr += nW) rows[nr++] = rr;
    for (int k = 0; k < nr; ++k) {
        u0[k] = g_unary[rows[k] * NC + lane];
        u1[k] = g_unary[rows[k] * NC + 32 + lane];
#pragma unroll
        for (int n = 0; n < KNN5; ++n) nb[k][n] = g_nbr[rows[k] * KNN5 + n];
    }

    float Eprev = __int_as_float(0x7f800000);
    int finalBuf = -1;

    for (int it = 0; it < MAXIT; ++it) {
        const float* __restrict__ Yin  = g_Ybuf[it & 1];
        float* __restrict__ Yout = g_Ybuf[(it + 1) & 1];

        float pw0[ROWS_MAX], pw1[ROWS_MAX];
#pragma unroll
        for (int k = 0; k < ROWS_MAX; ++k) {
            float a0 = 0.f, a1 = 0.f;
#pragma unroll
            for (int n = 0; n < KNN5; ++n) {
                const float* yr = Yin + (size_t)nb[k][n] * NC;
                a0 += yr[lane];
                a1 += yr[lane + 32];
            }
            pw0[k] = a0; pw1[k] = a1;
        }
        float x0[ROWS_MAX], x1[ROWS_MAX], m[ROWS_MAX], ssum[ROWS_MAX];
        float e0[ROWS_MAX], e1[ROWS_MAX];
#pragma unroll
        for (int k = 0; k < ROWS_MAX; ++k) {
            x0[k] = pw0[k] - u0[k]; x1[k] = pw1[k] - u1[k];
            m[k] = fmaxf(x0[k], x1[k]);
        }
#pragma unroll
        for (int o = 16; o > 0; o >>= 1)
#pragma unroll
            for (int k = 0; k < ROWS_MAX; ++k)
                m[k] = fmaxf(m[k], __shfl_xor_sync(0xffffffffu, m[k], o));
#pragma unroll
        for (int k = 0; k < ROWS_MAX; ++k) {
            e0[k] = __expf(x0[k] - m[k]); e1[k] = __expf(x1[k] - m[k]);
            ssum[k] = e0[k] + e1[k];
        }
#pragma unroll
        for (int o = 16; o > 0; o >>= 1)
#pragma unroll
            for (int k = 0; k < ROWS_MAX; ++k)
                ssum[k] += __shfl_xor_sync(0xffffffffu, ssum[k], o);

        float myE = 0.f;
#pragma unroll
        for (int k = 0; k < ROWS_MAX; ++k) {
            if (k < nr) {
                float inv = 1.0f / ssum[k];
                float y0 = e0[k] * inv, y1 = e1[k] * inv;
                const int rr = rows[k];
                Yout[rr * NC + lane]      = y0;
                Yout[rr * NC + 32 + lane] = y1;
                float ls = __logf(ssum[k]);
                myE += y0 * (u0[k] - pw0[k] + (x0[k] - m[k] - ls))
                     + y1 * (u1[k] - pw1[k] + (x1[k] - m[k] - ls));
            }
        }
#pragma unroll
        for (int o = 16; o > 0; o >>= 1) myE += __shfl_xor_sync(0xffffffffu, myE, o);
        if (lane == 0) sE[wib] = myE;
        __syncthreads();
        if (tid == 0) {
            float e = 0.f;
#pragma unroll
            for (int w = 0; w < IT_WARPS; ++w) e += sE[w];
            st_rel64(&g_slotE[(size_t)it * NB_IT + blockIdx.x],
                     ((uint64_t)1 << 32) | (uint64_t)__float_as_uint(e));
        }
        if (blockIdx.x == 0) {
            if (tid < NB_IT) {
                uint64_t v;
                do { v = ld_acq64(&g_slotE[(size_t)it * NB_IT + tid]); } while (!(v >> 32));
                sEarr[tid] = __uint_as_float((uint32_t)v);
            }
            __syncthreads();
            if (wib == 0) {
                const float* pe = sEarr;
                float e = pe[lane] + pe[lane + 32] + pe[lane + 64] + pe[lane + 96];
                if (lane < NB_IT - 128) e += pe[lane + 128];
#pragma unroll
                for (int o = 16; o > 0; o >>= 1) e += __shfl_xor_sync(0xffffffffu, e, o);
                if (lane == 0) {
                    sEbc = e;
                    st_rel64(&g_bcastE[it], ((uint64_t)1 << 32) | (uint64_t)__float_as_uint(e));
                }
            }
            __syncthreads();
        } else {
            if (tid == 0) {
                uint64_t v;
                do { v = ld_acq64(&g_bcastE[it]); } while (!(v >> 32));
                sEbc = __uint_as_float((uint32_t)v);
            }
            __syncthreads();
        }
        float E = sEbc;
        bool conv = (it > 1) && (fabsf(E - Eprev) <= 1e-8f * fabsf(Eprev));
        Eprev = E;
        if (conv) { finalBuf = (it + 1) & 1; break; }
        __syncthreads();
    }
    if (finalBuf < 0) finalBuf = MAXIT & 1;
    const float* __restrict__ Yf = g_Ybuf[finalBuf];
    for (int k = 0; k < nr; ++k) {
        const int rr = rows[k];
        dout[rr * NC + lane]      = Yf[rr * NC + lane];
        dout[rr * NC + 32 + lane] = Yf[rr * NC + 32 + lane];
    }
}

// ---------------- launch -----------------------------------------------------
extern "C" void kernel_launch(void* const* d_in, const int* in_sizes, int n_in,
                              void* d_out, int out_size) {
    const float* scores;
    const float* feats;
    if (in_sizes[0] == N * NC) { scores = (const float*)d_in[0]; feats = (const float*)d_in[1]; }
    else                       { scores = (const float*)d_in[1]; feats = (const float*)d_in[0]; }
    float* out = (float*)d_out;

    const int gram_smem = 3 * 32768;   // 96 KB
    cudaFuncSetAttribute(k_gram_mma, cudaFuncAttributeMaxDynamicSharedMemorySize, gram_smem);

    k_reset<<<(MAXIT * NB_IT + 255) / 256, 256>>>();
    k_prep_unary<<<N / 8, 256>>>(scores);
    k_prep_feats<<<N, 256>>>(feats);
    k_gram_mma<<<NBI * (NBI + 1) / 2, 256, gram_smem>>>();
    k_nn<<<N / 8, 256>>>();
    k_iterate<<<NB_IT, IT_THREADS>>>(out);
}

// round 9
// speedup vs baseline: 1.8033x; 1.8033x over previous
#include <cuda_runtime.h>
#include <cuda_bf16.h>
#include <math.h>
#include <stdint.h>

#define N      8192
#define D      256
#define NC     64
#define KNN5   5
#define TI     128
#define KC     64           // bf16 per smem stage (128 B/row)
#define NSTG   4            // K=256 / 64
#define NBI    (N/TI)       // 64 block-rows
#define NCAND  8            // approx candidates kept per tile
#define CAND   (NBI*NCAND)  // 512 candidate slots per row
#define CSTRIDE 133
#define NB_IT  148
#define IT_THREADS 512
#define IT_WARPS   16
#define ROWS_MAX   4
#define MAXIT  100
#define LAM    1.0f

// ---------------- scratch ----------------------------------------------------
__device__ __nv_bfloat16 g_H[(size_t)N * D];    // bf16(normalized feats)
__device__ float g_F[(size_t)N * D];            // fp32 normalized feats
__device__ float g_unary[N * NC];
__device__ float g_Ybuf[2][N * NC];
__device__ uint64_t g_cand[(size_t)N * CAND];   // packed {mapped_val:32 | (N-1-idx):32}
__device__ int   g_nbr[N * KNN5];
__device__ uint64_t g_slotE[(size_t)MAXIT * NB_IT];
__device__ uint64_t g_bcastE[MAXIT];

// ---------------- PTX helpers ------------------------------------------------
__device__ __forceinline__ uint32_t smem_u32(const void* p) {
    uint32_t a;
    asm("{ .reg .u64 t; cvta.to.shared.u64 t, %1; cvt.u32.u64 %0, t; }" : "=r"(a) : "l"(p));
    return a;
}
#define SWZ128(o) ((o) ^ (((o) >> 3) & 0x70))
#define CP_ASYNC16(dst, src) \
    asm volatile("cp.async.cg.shared.global [%0], [%1], 16;" :: "r"(dst), "l"(src) : "memory")
#define CP_COMMIT() asm volatile("cp.async.commit_group;" ::: "memory")
#define CP_WAIT(n)  asm volatile("cp.async.wait_group %0;" :: "n"(n) : "memory")
#define LDSM_X4(r0,r1,r2,r3, a) \
    asm volatile("ldmatrix.sync.aligned.m8n8.x4.shared.b16 {%0,%1,%2,%3}, [%4];" \
        : "=r"(r0),"=r"(r1),"=r"(r2),"=r"(r3) : "r"(a))
#define LDSM_X2(r0,r1, a) \
    asm volatile("ldmatrix.sync.aligned.m8n8.x2.shared.b16 {%0,%1}, [%2];" \
        : "=r"(r0),"=r"(r1) : "r"(a))
#define MMA16816(d, a, b) \
    asm volatile("mma.sync.aligned.m16n8k16.row.col.f32.bf16.bf16.f32 " \
        "{%0,%1,%2,%3}, {%4,%5,%6,%7}, {%8,%9}, {%0,%1,%2,%3};" \
        : "+f"((d)[0]),"+f"((d)[1]),"+f"((d)[2]),"+f"((d)[3]) \
        : "r"((a)[0]),"r"((a)[1]),"r"((a)[2]),"r"((a)[3]), "r"((b)[0]),"r"((b)[1]))

__device__ __forceinline__ void st_rel64(uint64_t* p, uint64_t v) {
    asm volatile("st.release.gpu.global.b64 [%0], %1;" :: "l"(p), "l"(v) : "memory");
}
__device__ __forceinline__ uint64_t ld_acq64(const uint64_t* p) {
    uint64_t v;
    asm volatile("ld.acquire.gpu.global.b64 %0, [%1];" : "=l"(v) : "l"(p) : "memory");
    return v;
}

// ---------------- packed-key top-8 -------------------------------------------
__device__ __forceinline__ uint64_t packKey(float v, int idx) {
    uint32_t b = __float_as_uint(v);
    b = (b & 0x80000000u) ? ~b : (b | 0x80000000u);   // order-preserving map
    return ((uint64_t)b << 32) | (uint32_t)(N - 1 - idx);
}
__device__ __forceinline__ int keyIdx(uint64_t k) { return N - 1 - (int)(uint32_t)k; }

__device__ __forceinline__ void ins8(uint64_t k, uint64_t* a) {
    if (k > a[7]) {
        a[7] = k;
#pragma unroll
        for (int s = 7; s > 0; --s)
            if (a[s] > a[s-1]) { uint64_t t = a[s]; a[s] = a[s-1]; a[s-1] = t; }
    }
}
template <int K>
__device__ __forceinline__ void topk_insert(float v, int j, float* bv, int* bi) {
    if (v > bv[K-1] || (v == bv[K-1] && j < bi[K-1])) {
        bv[K-1] = v; bi[K-1] = j;
#pragma unroll
        for (int s = K-1; s > 0; --s) {
            if (bv[s] > bv[s-1] || (bv[s] == bv[s-1] && bi[s] < bi[s-1])) {
                float tv = bv[s]; bv[s] = bv[s-1]; bv[s-1] = tv;
                int   tj = bi[s]; bi[s] = bi[s-1]; bi[s-1] = tj;
            }
        }
    }
}

// ---------------- reset sync slots (graph-replay safe) -----------------------
__global__ void k_reset() {
    int i = blockIdx.x * 256 + threadIdx.x;
    if (i < MAXIT * NB_IT) g_slotE[i] = 0ull;
    if (i < MAXIT) g_bcastE[i] = 0ull;
}

// ---------------- prep: unary + Y0 ------------------------------------------
__global__ void k_prep_unary(const float* __restrict__ scores) {
    int wib = threadIdx.x >> 5, lane = threadIdx.x & 31;
    int r = blockIdx.x * 8 + wib;
    const float* s = scores + (size_t)r * NC;
    float u0 = -logf(s[lane]      + 1e-10f);
    float u1 = -logf(s[lane + 32] + 1e-10f);
    g_unary[r * NC + lane]      = u0;
    g_unary[r * NC + 32 + lane] = u1;
    float x0 = -u0, x1 = -u1;
    float m = fmaxf(x0, x1);
#pragma unroll
    for (int o = 16; o > 0; o >>= 1) m = fmaxf(m, __shfl_xor_sync(0xffffffffu, m, o));
    float e0 = __expf(x0 - m), e1 = __expf(x1 - m);
    float t = e0 + e1;
#pragma unroll
    for (int o = 16; o > 0; o >>= 1) t += __shfl_xor_sync(0xffffffffu, t, o);
    float inv = 1.0f / t;
    g_Ybuf[0][r * NC + lane]      = e0 * inv;
    g_Ybuf[0][r * NC + 32 + lane] = e1 * inv;
}

// ---------------- prep: normalize -> fp32 + bf16 -----------------------------
__global__ void k_prep_feats(const float* __restrict__ feats) {
    __shared__ float red[8];
    __shared__ float nrmsh;
    int r = blockIdx.x, k = threadIdx.x;
    int lane = k & 31, w = k >> 5;
    float v = feats[(size_t)r * D + k];
    float s = v * v;
#pragma unroll
    for (int o = 16; o > 0; o >>= 1) s += __shfl_xor_sync(0xffffffffu, s, o);
    if (lane == 0) red[w] = s;
    __syncthreads();
    if (k == 0) {
        float t = 0.f;
#pragma unroll
        for (int i = 0; i < 8; ++i) t += red[i];
        nrmsh = sqrtf(t);
    }
    __syncthreads();
    float f = v / fmaxf(nrmsh, 1e-12f);
    g_F[(size_t)r * D + k] = f;
    g_H[(size_t)r * D + k] = __float2bfloat16(f);
}

// ---------------- bf16 Gram (K=256), upper-triangle, parallel top-8 ----------
// grid 2080 x 256; dynamic smem = 98304 B (3x32KB stages; 128x133 f32 epilogue)
__global__ void __launch_bounds__(256, 2) k_gram_mma() {
    extern __shared__ char smem[];
    float* Cs = (float*)smem;
    const uint32_t sb = smem_u32(smem);
    const int tid = threadIdx.x;
    const int lane = tid & 31, warp = tid >> 5;
    const int wm = warp >> 2, wn = warp & 3;

    int bi = 0, rem = blockIdx.x;
    while (rem >= NBI - bi) { rem -= NBI - bi; ++bi; }
    const int bj = bi + rem;
    const int ib = bi * TI, jb = bj * TI;

    float acc[4][4][4];
#pragma unroll
    for (int mf = 0; mf < 4; ++mf)
#pragma unroll
        for (int nf = 0; nf < 4; ++nf)
#pragma unroll
            for (int q = 0; q < 4; ++q) acc[mf][nf][q] = 0.f;

    const char* gH = (const char*)g_H;

#define LOAD_STAGE(sidx) do {                                                   \
        int _s = (sidx); uint32_t _b = (uint32_t)((sidx) % 3) * 32768u;         \
        _Pragma("unroll")                                                       \
        for (int t = 0; t < 4; ++t) {                                           \
            int e = tid + t * 256;                                              \
            int row = e >> 3, ch = e & 7;                                       \
            uint32_t off = SWZ128((uint32_t)(row * 128 + ch * 16));             \
            CP_ASYNC16(sb + _b + off,                                           \
                gH + ((size_t)(ib + row) * D + (size_t)_s * KC) * 2 + ch * 16); \
            CP_ASYNC16(sb + _b + 16384u + off,                                  \
                gH + ((size_t)(jb + row) * D + (size_t)_s * KC) * 2 + ch * 16); \
        }                                                                       \
        CP_COMMIT();                                                            \
    } while (0)

    LOAD_STAGE(0);
    LOAD_STAGE(1);

    for (int s = 0; s < NSTG; ++s) {
        if (s == NSTG - 1) { CP_WAIT(0); } else { CP_WAIT(1); }
        __syncthreads();
        if (s + 2 < NSTG) LOAD_STAGE(s + 2);

        const uint32_t aS = sb + (uint32_t)(s % 3) * 32768u;
        const uint32_t bS = aS + 16384u;
#pragma unroll
        for (int kk = 0; kk < 4; ++kk) {
            uint32_t a[4][4], b[4][2];
#pragma unroll
            for (int mf = 0; mf < 4; ++mf) {
                int row = wm * 64 + mf * 16 + (lane & 15);
                uint32_t kb = kk * 32 + ((lane >> 4) << 4);
                LDSM_X4(a[mf][0], a[mf][1], a[mf][2], a[mf][3], aS + SWZ128((uint32_t)(row * 128) + kb));
            }
#pragma unroll
            for (int nf = 0; nf < 4; ++nf) {
                int nrow = wn * 32 + nf * 8 + (lane & 7);
                uint32_t kb = kk * 32 + (((lane >> 3) & 1) << 4);
                LDSM_X2(b[nf][0], b[nf][1], bS + SWZ128((uint32_t)(nrow * 128) + kb));
            }
#pragma unroll
            for (int mf = 0; mf < 4; ++mf)
#pragma unroll
                for (int nf = 0; nf < 4; ++nf)
                    MMA16816(acc[mf][nf], a[mf], b[nf]);
        }
    }

    // dump ALL fragments -> smem (accumulators die; no register pressure after)
    __syncthreads();
#pragma unroll
    for (int mf = 0; mf < 4; ++mf)
#pragma unroll
        for (int nf = 0; nf < 4; ++nf) {
            int r0 = wm * 64 + mf * 16 + (lane >> 2);
            int c0 = wn * 32 + nf * 8 + 2 * (lane & 3);
            Cs[r0 * CSTRIDE + c0]           = acc[mf][nf][0];
            Cs[r0 * CSTRIDE + c0 + 1]       = acc[mf][nf][1];
            Cs[(r0 + 8) * CSTRIDE + c0]     = acc[mf][nf][2];
            Cs[(r0 + 8) * CSTRIDE + c0 + 1] = acc[mf][nf][3];
        }
    __syncthreads();

    // i-side: 2 threads per row; each scans 64 cols, pair-merge via shfl
    {
        const int row = tid >> 1, half = tid & 1;
        const int gi = ib + row;
        uint64_t k8[8] = {0,0,0,0,0,0,0,0};
        const int cb = half * 64;
        for (int c = cb; c < cb + 64; ++c) {
            int gj = jb + c;
            if (gj != gi) ins8(packKey(Cs[row * CSTRIDE + c], gj), k8);
        }
        uint64_t t8[8];
#pragma unroll
        for (int q = 0; q < 8; ++q) t8[q] = __shfl_xor_sync(0xffffffffu, k8[q], 1);
#pragma unroll
        for (int q = 0; q < 8; ++q) ins8(t8[q], k8);
        if (half == 0) {
#pragma unroll
            for (int q = 0; q < 8; ++q)
                g_cand[(size_t)gi * CAND + bj * NCAND + q] = k8[q];
        }
    }
    // j-side: 2 threads per col (off-diagonal tiles only)
    if (bi != bj) {
        const int col = tid >> 1, half = tid & 1;
        const int gj = jb + col;
        uint64_t k8[8] = {0,0,0,0,0,0,0,0};
        const int rb = half * 64;
        for (int r = rb; r < rb + 64; ++r)
            ins8(packKey(Cs[r * CSTRIDE + col], ib + r), k8);
        uint64_t t8[8];
#pragma unroll
        for (int q = 0; q < 8; ++q) t8[q] = __shfl_xor_sync(0xffffffffu, k8[q], 1);
#pragma unroll
        for (int q = 0; q < 8; ++q) ins8(t8[q], k8);
        if (half == 0) {
#pragma unroll
            for (int q = 0; q < 8; ++q)
                g_cand[(size_t)gj * CAND + bi * NCAND + q] = k8[q];
        }
    }
#undef LOAD_STAGE
}

// ---------------- merge + exact fp32 rescore -> final 5-NN -------------------
// warp per row; 1024 blocks x 256 threads
__global__ void __launch_bounds__(256) k_nn() {
    const int warp = threadIdx.x >> 5, lane = threadIdx.x & 31;
    const int r = blockIdx.x * 8 + warp;

    uint64_t k8[8] = {0,0,0,0,0,0,0,0};
    const size_t base = (size_t)r * CAND;
#pragma unroll
    for (int k = 0; k < CAND / 32; ++k)
        ins8(g_cand[base + lane + 32 * k], k8);
#pragma unroll
    for (int off = 16; off > 0; off >>= 1) {
        uint64_t t8[8];
#pragma unroll
        for (int q = 0; q < 8; ++q) t8[q] = __shfl_xor_sync(0xffffffffu, k8[q], off);
#pragma unroll
        for (int q = 0; q < 8; ++q) ins8(t8[q], k8);
    }

    // exact fp32 rescore of the 8 finalists
    float fr[8];
#pragma unroll
    for (int k = 0; k < 8; ++k) fr[k] = g_F[(size_t)r * D + lane + 32 * k];
    int   cidx[NCAND];
    float dots[NCAND];
#pragma unroll
    for (int q = 0; q < NCAND; ++q) {
        cidx[q] = keyIdx(k8[q]);
        const float* fc = g_F + (size_t)cidx[q] * D;
        float s = 0.f;
#pragma unroll
        for (int k = 0; k < 8; ++k) s = fmaf(fr[k], fc[lane + 32 * k], s);
#pragma unroll
        for (int o = 16; o > 0; o >>= 1) s += __shfl_xor_sync(0xffffffffu, s, o);
        dots[q] = s;
    }
    float b5[KNN5]; int i5[KNN5];
#pragma unroll
    for (int q = 0; q < KNN5; ++q) { b5[q] = -__int_as_float(0x7f800000); i5[q] = 0x7fffffff; }
#pragma unroll
    for (int q = 0; q < NCAND; ++q) topk_insert<KNN5>(dots[q], cidx[q], b5, i5);
    if (lane < KNN5) g_nbr[r * KNN5 + lane] = (i5[lane] >= 0 && i5[lane] < N) ? i5[lane] : 0;
}

// ---------------- persistent mean-field iteration (flag-based global sync) ---
__global__ void __launch_bounds__(IT_THREADS) k_iterate(float* __restrict__ dout) {
    __shared__ float sE[IT_WARPS];
    __shared__ float sEarr[NB_IT];
    __shared__ float sEbc;
    const int tid  = threadIdx.x;
    const int lane = tid & 31, wib = tid >> 5;
    const int warpG = blockIdx.x * IT_WARPS + wib;
    const int nW = NB_IT * IT_WARPS;

    int nr = 0, rows[ROWS_MAX];
    float u0[ROWS_MAX], u1[ROWS_MAX];
    int   nb[ROWS_MAX][KNN5];
#pragma unroll
    for (int k = 0; k < ROWS_MAX; ++k) {
        rows[k] = 0; u0[k] = 0.f; u1[k] = 0.f;
#pragma unroll
        for (int n = 0; n < KNN5; ++n) nb[k][n] = 0;
    }
    for (int rr = warpG; rr < N; rr += nW) rows[nr++] = rr;
    for (int k = 0; k < nr; ++k) {
        u0[k] = g_unary[rows[k] * NC + lane];
        u1[k] = g_unary[rows[k] * NC + 32 + lane];
#pragma unroll
        for (int n = 0; n < KNN5; ++n) nb[k][n] = g_nbr[rows[k] * KNN5 + n];
    }

    float Eprev = __int_as_float(0x7f800000);
    int finalBuf = -1;

    for (int it = 0; it < MAXIT; ++it) {
        const float* __restrict__ Yin  = g_Ybuf[it & 1];
        float* __restrict__ Yout = g_Ybuf[(it + 1) & 1];

        float pw0[ROWS_MAX], pw1[ROWS_MAX];
#pragma unroll
        for (int k = 0; k < ROWS_MAX; ++k) {
            float a0 = 0.f, a1 = 0.f;
#pragma unroll
            for (int n = 0; n < KNN5; ++n) {
                const float* yr = Yin + (size_t)nb[k][n] * NC;
                a0 += yr[lane];
                a1 += yr[lane + 32];
            }
            pw0[k] = a0; pw1[k] = a1;
        }
        float x0[ROWS_MAX], x1[ROWS_MAX], m[ROWS_MAX], ssum[ROWS_MAX];
        float e0[ROWS_MAX], e1[ROWS_MAX];
#pragma unroll
        for (int k = 0; k < ROWS_MAX; ++k) {
            x0[k] = pw0[k] - u0[k]; x1[k] = pw1[k] - u1[k];
            m[k] = fmaxf(x0[k], x1[k]);
        }
#pragma unroll
        for (int o = 16; o > 0; o >>= 1)
#pragma unroll
            for (int k = 0; k < ROWS_MAX; ++k)
                m[k] = fmaxf(m[k], __shfl_xor_sync(0xffffffffu, m[k], o));
#pragma unroll
        for (int k = 0; k < ROWS_MAX; ++k) {
            e0[k] = __expf(x0[k] - m[k]); e1[k] = __expf(x1[k] - m[k]);
            ssum[k] = e0[k] + e1[k];
        }
#pragma unroll
        for (int o = 16; o > 0; o >>= 1)
#pragma unroll
            for (int k = 0; k < ROWS_MAX; ++k)
                ssum[k] += __shfl_xor_sync(0xffffffffu, ssum[k], o);

        float myE = 0.f;
#pragma unroll
        for (int k = 0; k < ROWS_MAX; ++k) {
            if (k < nr) {
                float inv = 1.0f / ssum[k];
                float y0 = e0[k] * inv, y1 = e1[k] * inv;
                const int rr = rows[k];
                Yout[rr * NC + lane]      = y0;
                Yout[rr * NC + 32 + lane] = y1;
                float ls = __logf(ssum[k]);
                myE += y0 * (u0[k] - pw0[k] + (x0[k] - m[k] - ls))
                     + y1 * (u1[k] - pw1[k] + (x1[k] - m[k] - ls));
            }
        }
#pragma unroll
        for (int o = 16; o > 0; o >>= 1) myE += __shfl_xor_sync(0xffffffffu, myE, o);
        if (lane == 0) sE[wib] = myE;
        __syncthreads();
        if (tid == 0) {
            float e = 0.f;
#pragma unroll
            for (int w = 0; w < IT_WARPS; ++w) e += sE[w];
            st_rel64(&g_slotE[(size_t)it * NB_IT + blockIdx.x],
                     ((uint64_t)1 << 32) | (uint64_t)__float_as_uint(e));
        }
        if (blockIdx.x == 0) {
            if (tid < NB_IT) {
                uint64_t v;
                do { v = ld_acq64(&g_slotE[(size_t)it * NB_IT + tid]); } while (!(v >> 32));
                sEarr[tid] = __uint_as_float((uint32_t)v);
            }
            __syncthreads();
            if (wib == 0) {
                const float* pe = sEarr;
                float e = pe[lane] + pe[lane + 32] + pe[lane + 64] + pe[lane + 96];
                if (lane < NB_IT - 128) e += pe[lane + 128];
#pragma unroll
                for (int o = 16; o > 0; o >>= 1) e += __shfl_xor_sync(0xffffffffu, e, o);
                if (lane == 0) {
                    sEbc = e;
                    st_rel64(&g_bcastE[it], ((uint64_t)1 << 32) | (uint64_t)__float_as_uint(e));
                }
            }
            __syncthreads();
        } else {
            if (tid == 0) {
                uint64_t v;
                do { v = ld_acq64(&g_bcastE[it]); } while (!(v >> 32));
                sEbc = __uint_as_float((uint32_t)v);
            }
            __syncthreads();
        }
        float E = sEbc;
        bool conv = (it > 1) && (fabsf(E - Eprev) <= 1e-8f * fabsf(Eprev));
        Eprev = E;
        if (conv) { finalBuf = (it + 1) & 1; break; }
        __syncthreads();
    }
    if (finalBuf < 0) finalBuf = MAXIT & 1;
    const float* __restrict__ Yf = g_Ybuf[finalBuf];
    for (int k = 0; k < nr; ++k) {
        const int rr = rows[k];
        dout[rr * NC + lane]      = Yf[rr * NC + lane];
        dout[rr * NC + 32 + lane] = Yf[rr * NC + 32 + lane];
    }
}

// ---------------- launch -----------------------------------------------------
extern "C" void kernel_launch(void* const* d_in, const int* in_sizes, int n_in,
                              void* d_out, int out_size) {
    const float* scores;
    const float* feats;
    if (in_sizes[0] == N * NC) { scores = (const float*)d_in[0]; feats = (const float*)d_in[1]; }
    else                       { scores = (const float*)d_in[1]; feats = (const float*)d_in[0]; }
    float* out = (float*)d_out;

    const int gram_smem = 98304;   // 96 KB (stages 96KB / epilogue 68KB overlay)
    cudaFuncSetAttribute(k_gram_mma, cudaFuncAttributeMaxDynamicSharedMemorySize, gram_smem);

    k_reset<<<(MAXIT * NB_IT + 255) / 256, 256>>>();
    k_prep_unary<<<N / 8, 256>>>(scores);
    k_prep_feats<<<N, 256>>>(feats);
    k_gram_mma<<<NBI * (NBI + 1) / 2, 256, gram_smem>>>();
    k_nn<<<N / 8, 256>>>();
    k_iterate<<<NB_IT, IT_THREADS>>>(out);
}

// round 10
// speedup vs baseline: 4.6309x; 2.5681x over previous
#include <cuda_runtime.h>
#include <cuda_bf16.h>
#include <math.h>
#include <stdint.h>

#define N      8192
#define D      256
#define NC     64
#define KNN5   5
#define TI     128
#define KC     64           // bf16 per smem stage (128 B/row)
#define NSTG   4            // K=256 / 64
#define NBI    (N/TI)       // 64 block-rows
#define NCAND  8            // approx candidates kept per tile
#define CAND   (NBI*NCAND)  // 512 candidate slots per row
#define CSTRIDE 132         // float4-aligned epilogue stride
#define NB_IT  148
#define IT_THREADS 512
#define IT_WARPS   16
#define ROWS_MAX   4
#define MAXIT  100
#define LAM    1.0f

// ---------------- scratch ----------------------------------------------------
__device__ __nv_bfloat16 g_H[(size_t)N * D];    // bf16(normalized feats)
__device__ float g_F[(size_t)N * D];            // fp32 normalized feats
__device__ float g_unary[N * NC];
__device__ float g_Ybuf[2][N * NC];
__device__ uint32_t g_cand[(size_t)N * CAND];   // packed {val:19 | (8191-idx):13}
__device__ int   g_nbr[N * KNN5];
__device__ uint64_t g_slotE[(size_t)MAXIT * NB_IT];
__device__ uint64_t g_bcastE[MAXIT];

// ---------------- PTX helpers ------------------------------------------------
__device__ __forceinline__ uint32_t smem_u32(const void* p) {
    uint32_t a;
    asm("{ .reg .u64 t; cvta.to.shared.u64 t, %1; cvt.u32.u64 %0, t; }" : "=r"(a) : "l"(p));
    return a;
}
#define SWZ128(o) ((o) ^ (((o) >> 3) & 0x70))
#define CP_ASYNC16(dst, src) \
    asm volatile("cp.async.cg.shared.global [%0], [%1], 16;" :: "r"(dst), "l"(src) : "memory")
#define CP_COMMIT() asm volatile("cp.async.commit_group;" ::: "memory")
#define CP_WAIT(n)  asm volatile("cp.async.wait_group %0;" :: "n"(n) : "memory")
#define LDSM_X4(r0,r1,r2,r3, a) \
    asm volatile("ldmatrix.sync.aligned.m8n8.x4.shared.b16 {%0,%1,%2,%3}, [%4];" \
        : "=r"(r0),"=r"(r1),"=r"(r2),"=r"(r3) : "r"(a))
#define LDSM_X2(r0,r1, a) \
    asm volatile("ldmatrix.sync.aligned.m8n8.x2.shared.b16 {%0,%1}, [%2];" \
        : "=r"(r0),"=r"(r1) : "r"(a))
#define MMA16816(d, a, b) \
    asm volatile("mma.sync.aligned.m16n8k16.row.col.f32.bf16.bf16.f32 " \
        "{%0,%1,%2,%3}, {%4,%5,%6,%7}, {%8,%9}, {%0,%1,%2,%3};" \
        : "+f"((d)[0]),"+f"((d)[1]),"+f"((d)[2]),"+f"((d)[3]) \
        : "r"((a)[0]),"r"((a)[1]),"r"((a)[2]),"r"((a)[3]), "r"((b)[0]),"r"((b)[1]))

__device__ __forceinline__ void st_rel64(uint64_t* p, uint64_t v) {
    asm volatile("st.release.gpu.global.b64 [%0], %1;" :: "l"(p), "l"(v) : "memory");
}
__device__ __forceinline__ uint64_t ld_acq64(const uint64_t* p) {
    uint64_t v;
    asm volatile("ld.acquire.gpu.global.b64 %0, [%1];" : "=l"(v) : "l"(p) : "memory");
    return v;
}

// ---------------- packed u32 keys: {orderable_val:19 | (8191-idx):13} --------
__device__ __forceinline__ uint32_t packKey32(float v, int idx) {
    uint32_t b = __float_as_uint(v);
    b = (b & 0x80000000u) ? ~b : (b | 0x80000000u);   // order-preserving
    return (b & 0xFFFFE000u) | (uint32_t)(8191 - idx);
}
__device__ __forceinline__ int keyIdx32(uint32_t k) { return 8191 - (int)(k & 0x1FFFu); }
__device__ __forceinline__ float unpackLB32(uint32_t k) {   // bin lower bound
    uint32_t m = k & 0xFFFFE000u;
    uint32_t o = (m & 0x80000000u) ? (m & 0x7FFFFFFFu) : ~m;
    return __uint_as_float(o);
}
__device__ __forceinline__ void ins8_32(uint32_t k, uint32_t* a) {
    if (k > a[7]) {
        a[7] = k;
#pragma unroll
        for (int s = 7; s > 0; --s)
            if (a[s] > a[s-1]) { uint32_t t = a[s]; a[s] = a[s-1]; a[s-1] = t; }
    }
}
template <int K>
__device__ __forceinline__ void topk_insert(float v, int j, float* bv, int* bi) {
    if (v > bv[K-1] || (v == bv[K-1] && j < bi[K-1])) {
        bv[K-1] = v; bi[K-1] = j;
#pragma unroll
        for (int s = K-1; s > 0; --s) {
            if (bv[s] > bv[s-1] || (bv[s] == bv[s-1] && bi[s] < bi[s-1])) {
                float tv = bv[s]; bv[s] = bv[s-1]; bv[s-1] = tv;
                int   tj = bi[s]; bi[s] = bi[s-1]; bi[s-1] = tj;
            }
        }
    }
}

// ---------------- reset sync slots (graph-replay safe) -----------------------
__global__ void k_reset() {
    int i = blockIdx.x * 256 + threadIdx.x;
    if (i < MAXIT * NB_IT) g_slotE[i] = 0ull;
    if (i < MAXIT) g_bcastE[i] = 0ull;
}

// ---------------- prep: unary + Y0 ------------------------------------------
__global__ void k_prep_unary(const float* __restrict__ scores) {
    int wib = threadIdx.x >> 5, lane = threadIdx.x & 31;
    int r = blockIdx.x * 8 + wib;
    const float* s = scores + (size_t)r * NC;
    float u0 = -logf(s[lane]      + 1e-10f);
    float u1 = -logf(s[lane + 32] + 1e-10f);
    g_unary[r * NC + lane]      = u0;
    g_unary[r * NC + 32 + lane] = u1;
    float x0 = -u0, x1 = -u1;
    float m = fmaxf(x0, x1);
#pragma unroll
    for (int o = 16; o > 0; o >>= 1) m = fmaxf(m, __shfl_xor_sync(0xffffffffu, m, o));
    float e0 = __expf(x0 - m), e1 = __expf(x1 - m);
    float t = e0 + e1;
#pragma unroll
    for (int o = 16; o > 0; o >>= 1) t += __shfl_xor_sync(0xffffffffu, t, o);
    float inv = 1.0f / t;
    g_Ybuf[0][r * NC + lane]      = e0 * inv;
    g_Ybuf[0][r * NC + 32 + lane] = e1 * inv;
}

// ---------------- prep: normalize -> fp32 + bf16 -----------------------------
__global__ void k_prep_feats(const float* __restrict__ feats) {
    __shared__ float red[8];
    __shared__ float nrmsh;
    int r = blockIdx.x, k = threadIdx.x;
    int lane = k & 31, w = k >> 5;
    float v = feats[(size_t)r * D + k];
    float s = v * v;
#pragma unroll
    for (int o = 16; o > 0; o >>= 1) s += __shfl_xor_sync(0xffffffffu, s, o);
    if (lane == 0) red[w] = s;
    __syncthreads();
    if (k == 0) {
        float t = 0.f;
#pragma unroll
        for (int i = 0; i < 8; ++i) t += red[i];
        nrmsh = sqrtf(t);
    }
    __syncthreads();
    float f = v / fmaxf(nrmsh, 1e-12f);
    g_F[(size_t)r * D + k] = f;
    g_H[(size_t)r * D + k] = __float2bfloat16(f);
}

// ---------------- bf16 Gram (K=256), upper-triangle, prefiltered top-8 -------
// grid 2080 x 256; dynamic smem = 98304 B (3x32KB stages; 128x132 f32 epilogue)
__global__ void __launch_bounds__(256, 2) k_gram_mma() {
    extern __shared__ char smem[];
    float* Cs = (float*)smem;
    const uint32_t sb = smem_u32(smem);
    const int tid = threadIdx.x;
    const int lane = tid & 31, warp = tid >> 5;
    const int wm = warp >> 2, wn = warp & 3;

    int bi = 0, rem = blockIdx.x;
    while (rem >= NBI - bi) { rem -= NBI - bi; ++bi; }
    const int bj = bi + rem;
    const int ib = bi * TI, jb = bj * TI;

    float acc[4][4][4];
#pragma unroll
    for (int mf = 0; mf < 4; ++mf)
#pragma unroll
        for (int nf = 0; nf < 4; ++nf)
#pragma unroll
            for (int q = 0; q < 4; ++q) acc[mf][nf][q] = 0.f;

    const char* gH = (const char*)g_H;

#define LOAD_STAGE(sidx) do {                                                   \
        int _s = (sidx); uint32_t _b = (uint32_t)((sidx) % 3) * 32768u;         \
        _Pragma("unroll")                                                       \
        for (int t = 0; t < 4; ++t) {                                           \
            int e = tid + t * 256;                                              \
            int row = e >> 3, ch = e & 7;                                       \
            uint32_t off = SWZ128((uint32_t)(row * 128 + ch * 16));             \
            CP_ASYNC16(sb + _b + off,                                           \
                gH + ((size_t)(ib + row) * D + (size_t)_s * KC) * 2 + ch * 16); \
            CP_ASYNC16(sb + _b + 16384u + off,                                  \
                gH + ((size_t)(jb + row) * D + (size_t)_s * KC) * 2 + ch * 16); \
        }                                                                       \
        CP_COMMIT();                                                            \
    } while (0)

    LOAD_STAGE(0);
    LOAD_STAGE(1);

    for (int s = 0; s < NSTG; ++s) {
        if (s == NSTG - 1) { CP_WAIT(0); } else { CP_WAIT(1); }
        __syncthreads();
        if (s + 2 < NSTG) LOAD_STAGE(s + 2);

        const uint32_t aS = sb + (uint32_t)(s % 3) * 32768u;
        const uint32_t bS = aS + 16384u;
#pragma unroll
        for (int kk = 0; kk < 4; ++kk) {
            uint32_t a[4][4], b[4][2];
#pragma unroll
            for (int mf = 0; mf < 4; ++mf) {
                int row = wm * 64 + mf * 16 + (lane & 15);
                uint32_t kb = kk * 32 + ((lane >> 4) << 4);
                LDSM_X4(a[mf][0], a[mf][1], a[mf][2], a[mf][3], aS + SWZ128((uint32_t)(row * 128) + kb));
            }
#pragma unroll
            for (int nf = 0; nf < 4; ++nf) {
                int nrow = wn * 32 + nf * 8 + (lane & 7);
                uint32_t kb = kk * 32 + (((lane >> 3) & 1) << 4);
                LDSM_X2(b[nf][0], b[nf][1], bS + SWZ128((uint32_t)(nrow * 128) + kb));
            }
#pragma unroll
            for (int mf = 0; mf < 4; ++mf)
#pragma unroll
                for (int nf = 0; nf < 4; ++nf)
                    MMA16816(acc[mf][nf], a[mf], b[nf]);
        }
    }

    // dump ALL fragments -> smem (accumulators die)
    __syncthreads();
#pragma unroll
    for (int mf = 0; mf < 4; ++mf)
#pragma unroll
        for (int nf = 0; nf < 4; ++nf) {
            int r0 = wm * 64 + mf * 16 + (lane >> 2);
            int c0 = wn * 32 + nf * 8 + 2 * (lane & 3);
            Cs[r0 * CSTRIDE + c0]           = acc[mf][nf][0];
            Cs[r0 * CSTRIDE + c0 + 1]       = acc[mf][nf][1];
            Cs[(r0 + 8) * CSTRIDE + c0]     = acc[mf][nf][2];
            Cs[(r0 + 8) * CSTRIDE + c0 + 1] = acc[mf][nf][3];
        }
    __syncthreads();

    // i-side: 2 threads/row; float4 + fmax batch prefilter (fma pipe), then insert
    {
        const int row = tid >> 1, half = tid & 1;
        const int gi = ib + row;
        uint32_t k8[8] = {0,0,0,0,0,0,0,0};
        float th = -3.0e38f;
        const float* rowp = Cs + row * CSTRIDE + half * 64;
        const int cbase0 = jb + half * 64;
#pragma unroll 4
        for (int c4 = 0; c4 < 16; ++c4) {
            float4 v = *(const float4*)(rowp + c4 * 4);
            float bm = fmaxf(fmaxf(v.x, v.y), fmaxf(v.z, v.w));
            if (bm > th) {
                int cb = cbase0 + c4 * 4;
                if (cb + 0 != gi && v.x > th) ins8_32(packKey32(v.x, cb + 0), k8);
                if (cb + 1 != gi && v.y > th) ins8_32(packKey32(v.y, cb + 1), k8);
                if (cb + 2 != gi && v.z > th) ins8_32(packKey32(v.z, cb + 2), k8);
                if (cb + 3 != gi && v.w > th) ins8_32(packKey32(v.w, cb + 3), k8);
                th = k8[7] ? unpackLB32(k8[7]) : -3.0e38f;
            }
        }
        uint32_t t8[8];
#pragma unroll
        for (int q = 0; q < 8; ++q) t8[q] = __shfl_xor_sync(0xffffffffu, k8[q], 1);
#pragma unroll
        for (int q = 0; q < 8; ++q) ins8_32(t8[q], k8);
        if (half == 0) {
#pragma unroll
            for (int q = 0; q < 8; ++q)
                g_cand[(size_t)gi * CAND + bj * NCAND + q] = k8[q];
        }
    }
    // j-side: 2 threads/col (off-diagonal tiles only)
    if (bi != bj) {
        const int col = tid >> 1, half = tid & 1;
        const int gj = jb + col;
        uint32_t k8[8] = {0,0,0,0,0,0,0,0};
        float th = -3.0e38f;
        const float* colp = Cs + (half * 64) * CSTRIDE + col;
        const int rbase0 = ib + half * 64;
#pragma unroll 4
        for (int r4 = 0; r4 < 16; ++r4) {
            float v0 = colp[(r4 * 4 + 0) * CSTRIDE];
            float v1 = colp[(r4 * 4 + 1) * CSTRIDE];
            float v2 = colp[(r4 * 4 + 2) * CSTRIDE];
            float v3 = colp[(r4 * 4 + 3) * CSTRIDE];
            float bm = fmaxf(fmaxf(v0, v1), fmaxf(v2, v3));
            if (bm > th) {
                int rb = rbase0 + r4 * 4;
                if (v0 > th) ins8_32(packKey32(v0, rb + 0), k8);
                if (v1 > th) ins8_32(packKey32(v1, rb + 1), k8);
                if (v2 > th) ins8_32(packKey32(v2, rb + 2), k8);
                if (v3 > th) ins8_32(packKey32(v3, rb + 3), k8);
                th = k8[7] ? unpackLB32(k8[7]) : -3.0e38f;
            }
        }
        uint32_t t8[8];
#pragma unroll
        for (int q = 0; q < 8; ++q) t8[q] = __shfl_xor_sync(0xffffffffu, k8[q], 1);
#pragma unroll
        for (int q = 0; q < 8; ++q) ins8_32(t8[q], k8);
        if (half == 0) {
#pragma unroll
            for (int q = 0; q < 8; ++q)
                g_cand[(size_t)gj * CAND + bi * NCAND + q] = k8[q];
        }
    }
#undef LOAD_STAGE
}

// ---------------- merge + exact fp32 rescore -> final 5-NN -------------------
// warp per row; 1024 blocks x 256 threads
__global__ void __launch_bounds__(256) k_nn() {
    const int warp = threadIdx.x >> 5, lane = threadIdx.x & 31;
    const int r = blockIdx.x * 8 + warp;

    uint32_t k8[8] = {0,0,0,0,0,0,0,0};
    const size_t base = (size_t)r * CAND;
#pragma unroll
    for (int k = 0; k < CAND / 32; ++k)
        ins8_32(g_cand[base + lane + 32 * k], k8);
#pragma unroll
    for (int off = 16; off > 0; off >>= 1) {
        uint32_t t8[8];
#pragma unroll
        for (int q = 0; q < 8; ++q) t8[q] = __shfl_xor_sync(0xffffffffu, k8[q], off);
#pragma unroll
        for (int q = 0; q < 8; ++q) ins8_32(t8[q], k8);
    }

    // exact fp32 rescore of the 8 finalists
    float fr[8];
#pragma unroll
    for (int k = 0; k < 8; ++k) fr[k] = g_F[(size_t)r * D + lane + 32 * k];
    int   cidx[NCAND];
    float dots[NCAND];
#pragma unroll
    for (int q = 0; q < NCAND; ++q) {
        cidx[q] = keyIdx32(k8[q]);
        const float* fc = g_F + (size_t)cidx[q] * D;
        float s = 0.f;
#pragma unroll
        for (int k = 0; k < 8; ++k) s = fmaf(fr[k], fc[lane + 32 * k], s);
#pragma unroll
        for (int o = 16; o > 0; o >>= 1) s += __shfl_xor_sync(0xffffffffu, s, o);
        dots[q] = s;
    }
    float b5[KNN5]; int i5[KNN5];
#pragma unroll
    for (int q = 0; q < KNN5; ++q) { b5[q] = -__int_as_float(0x7f800000); i5[q] = 0x7fffffff; }
#pragma unroll
    for (int q = 0; q < NCAND; ++q) topk_insert<KNN5>(dots[q], cidx[q], b5, i5);
    if (lane < KNN5) g_nbr[r * KNN5 + lane] = (i5[lane] >= 0 && i5[lane] < N) ? i5[lane] : 0;
}

// ---------------- persistent mean-field iteration (flag-based global sync) ---
__global__ void __launch_bounds__(IT_THREADS) k_iterate(float* __restrict__ dout) {
    __shared__ float sE[IT_WARPS];
    __shared__ float sEarr[NB_IT];
    __shared__ float sEbc;
    const int tid  = threadIdx.x;
    const int lane = tid & 31, wib = tid >> 5;
    const int warpG = blockIdx.x * IT_WARPS + wib;
    const int nW = NB_IT * IT_WARPS;

    int nr = 0, rows[ROWS_MAX];
    float u0[ROWS_MAX], u1[ROWS_MAX];
    int   nb[ROWS_MAX][KNN5];
#pragma unroll
    for (int k = 0; k < ROWS_MAX; ++k) {
        rows[k] = 0; u0[k] = 0.f; u1[k] = 0.f;
#pragma unroll
        for (int n = 0; n < KNN5; ++n) nb[k][n] = 0;
    }
    for (int rr = warpG; rr < N; rr += nW) rows[nr++] = rr;
    for (int k = 0; k < nr; ++k) {
        u0[k] = g_unary[rows[k] * NC + lane];
        u1[k] = g_unary[rows[k] * NC + 32 + lane];
#pragma unroll
        for (int n = 0; n < KNN5; ++n) nb[k][n] = g_nbr[rows[k] * KNN5 + n];
    }

    float Eprev = __int_as_float(0x7f800000);
    int finalBuf = -1;

    for (int it = 0; it < MAXIT; ++it) {
        const float* __restrict__ Yin  = g_Ybuf[it & 1];
        float* __restrict__ Yout = g_Ybuf[(it + 1) & 1];

        float pw0[ROWS_MAX], pw1[ROWS_MAX];
#pragma unroll
        for (int k = 0; k < ROWS_MAX; ++k) {
            float a0 = 0.f, a1 = 0.f;
#pragma unroll
            for (int n = 0; n < KNN5; ++n) {
                const float* yr = Yin + (size_t)nb[k][n] * NC;
                a0 += yr[lane];
                a1 += yr[lane + 32];
            }
            pw0[k] = a0; pw1[k] = a1;
        }
        float x0[ROWS_MAX], x1[ROWS_MAX], m[ROWS_MAX], ssum[ROWS_MAX];
        float e0[ROWS_MAX], e1[ROWS_MAX];
#pragma unroll
        for (int k = 0; k < ROWS_MAX; ++k) {
            x0[k] = pw0[k] - u0[k]; x1[k] = pw1[k] - u1[k];
            m[k] = fmaxf(x0[k], x1[k]);
        }
#pragma unroll
        for (int o = 16; o > 0; o >>= 1)
#pragma unroll
            for (int k = 0; k < ROWS_MAX; ++k)
                m[k] = fmaxf(m[k], __shfl_xor_sync(0xffffffffu, m[k], o));
#pragma unroll
        for (int k = 0; k < ROWS_MAX; ++k) {
            e0[k] = __expf(x0[k] - m[k]); e1[k] = __expf(x1[k] - m[k]);
            ssum[k] = e0[k] + e1[k];
        }
#pragma unroll
        for (int o = 16; o > 0; o >>= 1)
#pragma unroll
            for (int k = 0; k < ROWS_MAX; ++k)
                ssum[k] += __shfl_xor_sync(0xffffffffu, ssum[k], o);

        float myE = 0.f;
#pragma unroll
        for (int k = 0; k < ROWS_MAX; ++k) {
            if (k < nr) {
                float inv = 1.0f / ssum[k];
                float y0 = e0[k] * inv, y1 = e1[k] * inv;
                const int rr = rows[k];
                Yout[rr * NC + lane]      = y0;
                Yout[rr * NC + 32 + lane] = y1;
                float ls = __logf(ssum[k]);
                myE += y0 * (u0[k] - pw0[k] + (x0[k] - m[k] - ls))
                     + y1 * (u1[k] - pw1[k] + (x1[k] - m[k] - ls));
            }
        }
#pragma unroll
        for (int o = 16; o > 0; o >>= 1) myE += __shfl_xor_sync(0xffffffffu, myE, o);
        if (lane == 0) sE[wib] = myE;
        __syncthreads();
        if (tid == 0) {
            float e = 0.f;
#pragma unroll
            for (int w = 0; w < IT_WARPS; ++w) e += sE[w];
            st_rel64(&g_slotE[(size_t)it * NB_IT + blockIdx.x],
                     ((uint64_t)1 << 32) | (uint64_t)__float_as_uint(e));
        }
        if (blockIdx.x == 0) {
            if (tid < NB_IT) {
                uint64_t v;
                do { v = ld_acq64(&g_slotE[(size_t)it * NB_IT + tid]); } while (!(v >> 32));
                sEarr[tid] = __uint_as_float((uint32_t)v);
            }
            __syncthreads();
            if (wib == 0) {
                const float* pe = sEarr;
                float e = pe[lane] + pe[lane + 32] + pe[lane + 64] + pe[lane + 96];
                if (lane < NB_IT - 128) e += pe[lane + 128];
#pragma unroll
                for (int o = 16; o > 0; o >>= 1) e += __shfl_xor_sync(0xffffffffu, e, o);
                if (lane == 0) {
                    sEbc = e;
                    st_rel64(&g_bcastE[it], ((uint64_t)1 << 32) | (uint64_t)__float_as_uint(e));
                }
            }
            __syncthreads();
        } else {
            if (tid == 0) {
                uint64_t v;
                do { v = ld_acq64(&g_bcastE[it]); } while (!(v >> 32));
                sEbc = __uint_as_float((uint32_t)v);
            }
            __syncthreads();
        }
        float E = sEbc;
        bool conv = (it > 1) && (fabsf(E - Eprev) <= 1e-8f * fabsf(Eprev));
        Eprev = E;
        if (conv) { finalBuf = (it + 1) & 1; break; }
        __syncthreads();
    }
    if (finalBuf < 0) finalBuf = MAXIT & 1;
    const float* __restrict__ Yf = g_Ybuf[finalBuf];
    for (int k = 0; k < nr; ++k) {
        const int rr = rows[k];
        dout[rr * NC + lane]      = Yf[rr * NC + lane];
        dout[rr * NC + 32 + lane] = Yf[rr * NC + 32 + lane];
    }
}

// ---------------- launch -----------------------------------------------------
extern "C" void kernel_launch(void* const* d_in, const int* in_sizes, int n_in,
                              void* d_out, int out_size) {
    const float* scores;
    const float* feats;
    if (in_sizes[0] == N * NC) { scores = (const float*)d_in[0]; feats = (const float*)d_in[1]; }
    else                       { scores = (const float*)d_in[1]; feats = (const float*)d_in[0]; }
    float* out = (float*)d_out;

    const int gram_smem = 98304;   // 96 KB (stages) / 128x132 f32 epilogue overlay
    cudaFuncSetAttribute(k_gram_mma, cudaFuncAttributeMaxDynamicSharedMemorySize, gram_smem);

    k_reset<<<(MAXIT * NB_IT + 255) / 256, 256>>>();
    k_prep_unary<<<N / 8, 256>>>(scores);
    k_prep_feats<<<N, 256>>>(feats);
    k_gram_mma<<<NBI * (NBI + 1) / 2, 256, gram_smem>>>();
    k_nn<<<N / 8, 256>>>();
    k_iterate<<<NB_IT, IT_THREADS>>>(out);
}

// round 11
// speedup vs baseline: 4.7484x; 1.0254x over previous
#include <cuda_runtime.h>
#include <cuda_bf16.h>
#include <math.h>
#include <stdint.h>

#define N      8192
#define D      256
#define NC     64
#define KNN5   5
#define TI     128
#define KC     64           // bf16 per smem stage (128 B/row)
#define NSTG   4            // K=256 / 64
#define NBI    (N/TI)       // 64 block-rows
#define NCAND  8            // approx candidates kept per tile
#define CAND   (NBI*NCAND)  // 512 candidate slots per row
#define CSTRIDE 132         // float4-aligned epilogue stride
#define NB_IT  148
#define IT_THREADS 512
#define IT_WARPS   16
#define ROWS_MAX   4
#define MAXIT  100
#define LAM    1.0f

// ---------------- scratch ----------------------------------------------------
__device__ __nv_bfloat16 g_H[(size_t)N * D];    // bf16(normalized feats)
__device__ float g_F[(size_t)N * D];            // fp32 normalized feats
__device__ float g_unary[N * NC];
__device__ float g_Ybuf[2][N * NC];
__device__ uint32_t g_cand[(size_t)N * CAND];   // packed {val:19 | (8191-idx):13}
__device__ int   g_nbr[N * KNN5];
__device__ uint64_t g_slotE[(size_t)MAXIT * NB_IT];
__device__ uint64_t g_bcastE[MAXIT];

// ---------------- PTX helpers ------------------------------------------------
__device__ __forceinline__ uint32_t smem_u32(const void* p) {
    uint32_t a;
    asm("{ .reg .u64 t; cvta.to.shared.u64 t, %1; cvt.u32.u64 %0, t; }" : "=r"(a) : "l"(p));
    return a;
}
#define SWZ128(o) ((o) ^ (((o) >> 3) & 0x70))
#define CP_ASYNC16(dst, src) \
    asm volatile("cp.async.cg.shared.global [%0], [%1], 16;" :: "r"(dst), "l"(src) : "memory")
#define CP_COMMIT() asm volatile("cp.async.commit_group;" ::: "memory")
#define CP_WAIT(n)  asm volatile("cp.async.wait_group %0;" :: "n"(n) : "memory")
#define LDSM_X4(r0,r1,r2,r3, a) \
    asm volatile("ldmatrix.sync.aligned.m8n8.x4.shared.b16 {%0,%1,%2,%3}, [%4];" \
        : "=r"(r0),"=r"(r1),"=r"(r2),"=r"(r3) : "r"(a))
#define LDSM_X2(r0,r1, a) \
    asm volatile("ldmatrix.sync.aligned.m8n8.x2.shared.b16 {%0,%1}, [%2];" \
        : "=r"(r0),"=r"(r1) : "r"(a))
#define MMA16816(d, a, b) \
    asm volatile("mma.sync.aligned.m16n8k16.row.col.f32.bf16.bf16.f32 " \
        "{%0,%1,%2,%3}, {%4,%5,%6,%7}, {%8,%9}, {%0,%1,%2,%3};" \
        : "+f"((d)[0]),"+f"((d)[1]),"+f"((d)[2]),"+f"((d)[3]) \
        : "r"((a)[0]),"r"((a)[1]),"r"((a)[2]),"r"((a)[3]), "r"((b)[0]),"r"((b)[1]))

__device__ __forceinline__ void st_rel64(uint64_t* p, uint64_t v) {
    asm volatile("st.release.gpu.global.b64 [%0], %1;" :: "l"(p), "l"(v) : "memory");
}
__device__ __forceinline__ uint64_t ld_acq64(const uint64_t* p) {
    uint64_t v;
    asm volatile("ld.acquire.gpu.global.b64 %0, [%1];" : "=l"(v) : "l"(p) : "memory");
    return v;
}

// ---------------- packed u32 keys: {orderable_val:19 | (8191-idx):13} --------
__device__ __forceinline__ uint32_t packKey32(float v, int idx) {
    uint32_t b = __float_as_uint(v);
    b = (b & 0x80000000u) ? ~b : (b | 0x80000000u);   // order-preserving
    return (b & 0xFFFFE000u) | (uint32_t)(8191 - idx);
}
__device__ __forceinline__ int keyIdx32(uint32_t k) { return 8191 - (int)(k & 0x1FFFu); }
__device__ __forceinline__ float unpackLB32(uint32_t k) {   // bin lower bound
    uint32_t m = k & 0xFFFFE000u;
    uint32_t o = (m & 0x80000000u) ? (m & 0x7FFFFFFFu) : ~m;
    return __uint_as_float(o);
}
__device__ __forceinline__ void ins8_32(uint32_t k, uint32_t* a) {
    if (k > a[7]) {
        a[7] = k;
#pragma unroll
        for (int s = 7; s > 0; --s)
            if (a[s] > a[s-1]) { uint32_t t = a[s]; a[s] = a[s-1]; a[s-1] = t; }
    }
}
template <int K>
__device__ __forceinline__ void topk_insert(float v, int j, float* bv, int* bi) {
    if (v > bv[K-1] || (v == bv[K-1] && j < bi[K-1])) {
        bv[K-1] = v; bi[K-1] = j;
#pragma unroll
        for (int s = K-1; s > 0; --s) {
            if (bv[s] > bv[s-1] || (bv[s] == bv[s-1] && bi[s] < bi[s-1])) {
                float tv = bv[s]; bv[s] = bv[s-1]; bv[s-1] = tv;
                int   tj = bi[s]; bi[s] = bi[s-1]; bi[s-1] = tj;
            }
        }
    }
}

// ---------------- prep: unary + Y0 (+ sync-slot reset, graph-replay safe) ----
__global__ void k_prep_unary(const float* __restrict__ scores) {
    int wib = threadIdx.x >> 5, lane = threadIdx.x & 31;
    int r = blockIdx.x * 8 + wib;
    // fold reset of flag slots into this launch
    int gidx = blockIdx.x * 256 + threadIdx.x;
    if (gidx < MAXIT * NB_IT) g_slotE[gidx] = 0ull;
    if (gidx < MAXIT) g_bcastE[gidx] = 0ull;

    const float* s = scores + (size_t)r * NC;
    float u0 = -logf(s[lane]      + 1e-10f);
    float u1 = -logf(s[lane + 32] + 1e-10f);
    g_unary[r * NC + lane]      = u0;
    g_unary[r * NC + 32 + lane] = u1;
    float x0 = -u0, x1 = -u1;
    float m = fmaxf(x0, x1);
#pragma unroll
    for (int o = 16; o > 0; o >>= 1) m = fmaxf(m, __shfl_xor_sync(0xffffffffu, m, o));
    float e0 = __expf(x0 - m), e1 = __expf(x1 - m);
    float t = e0 + e1;
#pragma unroll
    for (int o = 16; o > 0; o >>= 1) t += __shfl_xor_sync(0xffffffffu, t, o);
    float inv = 1.0f / t;
    g_Ybuf[0][r * NC + lane]      = e0 * inv;
    g_Ybuf[0][r * NC + 32 + lane] = e1 * inv;
}

// ---------------- prep: normalize -> fp32 + bf16 -----------------------------
__global__ void k_prep_feats(const float* __restrict__ feats) {
    __shared__ float red[8];
    __shared__ float nrmsh;
    int r = blockIdx.x, k = threadIdx.x;
    int lane = k & 31, w = k >> 5;
    float v = feats[(size_t)r * D + k];
    float s = v * v;
#pragma unroll
    for (int o = 16; o > 0; o >>= 1) s += __shfl_xor_sync(0xffffffffu, s, o);
    if (lane == 0) red[w] = s;
    __syncthreads();
    if (k == 0) {
        float t = 0.f;
#pragma unroll
        for (int i = 0; i < 8; ++i) t += red[i];
        nrmsh = sqrtf(t);
    }
    __syncthreads();
    float f = v / fmaxf(nrmsh, 1e-12f);
    g_F[(size_t)r * D + k] = f;
    g_H[(size_t)r * D + k] = __float2bfloat16(f);
}

// ---------------- bf16 Gram (K=256), upper-triangle, interleaved top-8 -------
// grid 2080 x 256; dynamic smem = 98304 B (3x32KB stages; 128x132 f32 epilogue)
__global__ void __launch_bounds__(256, 2) k_gram_mma() {
    extern __shared__ char smem[];
    float* Cs = (float*)smem;
    const uint32_t sb = smem_u32(smem);
    const int tid = threadIdx.x;
    const int lane = tid & 31, warp = tid >> 5;
    const int wm = warp >> 2, wn = warp & 3;

    int bi = 0, rem = blockIdx.x;
    while (rem >= NBI - bi) { rem -= NBI - bi; ++bi; }
    const int bj = bi + rem;
    const int ib = bi * TI, jb = bj * TI;

    float acc[4][4][4];
#pragma unroll
    for (int mf = 0; mf < 4; ++mf)
#pragma unroll
        for (int nf = 0; nf < 4; ++nf)
#pragma unroll
            for (int q = 0; q < 4; ++q) acc[mf][nf][q] = 0.f;

    const char* gH = (const char*)g_H;

#define LOAD_STAGE(sidx) do {                                                   \
        int _s = (sidx); uint32_t _b = (uint32_t)((sidx) % 3) * 32768u;         \
        _Pragma("unroll")                                                       \
        for (int t = 0; t < 4; ++t) {                                           \
            int e = tid + t * 256;                                              \
            int row = e >> 3, ch = e & 7;                                       \
            uint32_t off = SWZ128((uint32_t)(row * 128 + ch * 16));             \
            CP_ASYNC16(sb + _b + off,                                           \
                gH + ((size_t)(ib + row) * D + (size_t)_s * KC) * 2 + ch * 16); \
            CP_ASYNC16(sb + _b + 16384u + off,                                  \
                gH + ((size_t)(jb + row) * D + (size_t)_s * KC) * 2 + ch * 16); \
        }                                                                       \
        CP_COMMIT();                                                            \
    } while (0)

    LOAD_STAGE(0);
    LOAD_STAGE(1);

    for (int s = 0; s < NSTG; ++s) {
        if (s == NSTG - 1) { CP_WAIT(0); } else { CP_WAIT(1); }
        __syncthreads();
        if (s + 2 < NSTG) LOAD_STAGE(s + 2);

        const uint32_t aS = sb + (uint32_t)(s % 3) * 32768u;
        const uint32_t bS = aS + 16384u;
#pragma unroll
        for (int kk = 0; kk < 4; ++kk) {
            uint32_t a[4][4], b[4][2];
#pragma unroll
            for (int mf = 0; mf < 4; ++mf) {
                int row = wm * 64 + mf * 16 + (lane & 15);
                uint32_t kb = kk * 32 + ((lane >> 4) << 4);
                LDSM_X4(a[mf][0], a[mf][1], a[mf][2], a[mf][3], aS + SWZ128((uint32_t)(row * 128) + kb));
            }
#pragma unroll
            for (int nf = 0; nf < 4; ++nf) {
                int nrow = wn * 32 + nf * 8 + (lane & 7);
                uint32_t kb = kk * 32 + (((lane >> 3) & 1) << 4);
                LDSM_X2(b[nf][0], b[nf][1], bS + SWZ128((uint32_t)(nrow * 128) + kb));
            }
#pragma unroll
            for (int mf = 0; mf < 4; ++mf)
#pragma unroll
                for (int nf = 0; nf < 4; ++nf)
                    MMA16816(acc[mf][nf], a[mf], b[nf]);
        }
    }

    // dump ALL fragments -> smem (accumulators die)
    __syncthreads();
#pragma unroll
    for (int mf = 0; mf < 4; ++mf)
#pragma unroll
        for (int nf = 0; nf < 4; ++nf) {
            int r0 = wm * 64 + mf * 16 + (lane >> 2);
            int c0 = wn * 32 + nf * 8 + 2 * (lane & 3);
            Cs[r0 * CSTRIDE + c0]           = acc[mf][nf][0];
            Cs[r0 * CSTRIDE + c0 + 1]       = acc[mf][nf][1];
            Cs[(r0 + 8) * CSTRIDE + c0]     = acc[mf][nf][2];
            Cs[(r0 + 8) * CSTRIDE + c0 + 1] = acc[mf][nf][3];
        }
    __syncthreads();

    if (bi != bj) {
        // off-diagonal: interleaved i-side (rows) + j-side (cols) scans.
        // No self-exclusion needed (gi never in j-block).
        const int row = tid >> 1, half = tid & 1;
        const int gi = ib + row;
        const int gj = jb + row;
        uint32_t k8i[8] = {0,0,0,0,0,0,0,0};
        uint32_t k8j[8] = {0,0,0,0,0,0,0,0};
        float thi = -3.0e38f, thj = -3.0e38f;
        const float* rowp = Cs + row * CSTRIDE + half * 64;
        const float* colp = Cs + (half * 64) * CSTRIDE + row;
        const int cbase0 = jb + half * 64;
        const int rbase0 = ib + half * 64;
#pragma unroll 4
        for (int c4 = 0; c4 < 16; ++c4) {
            float4 v = *(const float4*)(rowp + c4 * 4);
            float w0 = colp[(c4 * 4 + 0) * CSTRIDE];
            float w1 = colp[(c4 * 4 + 1) * CSTRIDE];
            float w2 = colp[(c4 * 4 + 2) * CSTRIDE];
            float w3 = colp[(c4 * 4 + 3) * CSTRIDE];
            float bmi = fmaxf(fmaxf(v.x, v.y), fmaxf(v.z, v.w));
            float bmj = fmaxf(fmaxf(w0, w1), fmaxf(w2, w3));
            if (bmi > thi) {
                int cb = cbase0 + c4 * 4;
                if (v.x > thi) ins8_32(packKey32(v.x, cb + 0), k8i);
                if (v.y > thi) ins8_32(packKey32(v.y, cb + 1), k8i);
                if (v.z > thi) ins8_32(packKey32(v.z, cb + 2), k8i);
                if (v.w > thi) ins8_32(packKey32(v.w, cb + 3), k8i);
                thi = k8i[7] ? unpackLB32(k8i[7]) : -3.0e38f;
            }
            if (bmj > thj) {
                int rb = rbase0 + c4 * 4;
                if (w0 > thj) ins8_32(packKey32(w0, rb + 0), k8j);
                if (w1 > thj) ins8_32(packKey32(w1, rb + 1), k8j);
                if (w2 > thj) ins8_32(packKey32(w2, rb + 2), k8j);
                if (w3 > thj) ins8_32(packKey32(w3, rb + 3), k8j);
                thj = k8j[7] ? unpackLB32(k8j[7]) : -3.0e38f;
            }
        }
        uint32_t t8[8];
#pragma unroll
        for (int q = 0; q < 8; ++q) t8[q] = __shfl_xor_sync(0xffffffffu, k8i[q], 1);
#pragma unroll
        for (int q = 0; q < 8; ++q) ins8_32(t8[q], k8i);
#pragma unroll
        for (int q = 0; q < 8; ++q) t8[q] = __shfl_xor_sync(0xffffffffu, k8j[q], 1);
#pragma unroll
        for (int q = 0; q < 8; ++q) ins8_32(t8[q], k8j);
        if (half == 0) {
#pragma unroll
            for (int q = 0; q < 8; ++q) {
                g_cand[(size_t)gi * CAND + bj * NCAND + q] = k8i[q];
                g_cand[(size_t)gj * CAND + bi * NCAND + q] = k8j[q];
            }
        }
    } else {
        // diagonal: i-side only, with self-exclusion
        const int row = tid >> 1, half = tid & 1;
        const int gi = ib + row;
        uint32_t k8[8] = {0,0,0,0,0,0,0,0};
        float th = -3.0e38f;
        const float* rowp = Cs + row * CSTRIDE + half * 64;
        const int cbase0 = jb + half * 64;
#pragma unroll 4
        for (int c4 = 0; c4 < 16; ++c4) {
            float4 v = *(const float4*)(rowp + c4 * 4);
            float bm = fmaxf(fmaxf(v.x, v.y), fmaxf(v.z, v.w));
            if (bm > th) {
                int cb = cbase0 + c4 * 4;
                if (cb + 0 != gi && v.x > th) ins8_32(packKey32(v.x, cb + 0), k8);
                if (cb + 1 != gi && v.y > th) ins8_32(packKey32(v.y, cb + 1), k8);
                if (cb + 2 != gi && v.z > th) ins8_32(packKey32(v.z, cb + 2), k8);
                if (cb + 3 != gi && v.w > th) ins8_32(packKey32(v.w, cb + 3), k8);
                th = k8[7] ? unpackLB32(k8[7]) : -3.0e38f;
            }
        }
        uint32_t t8[8];
#pragma unroll
        for (int q = 0; q < 8; ++q) t8[q] = __shfl_xor_sync(0xffffffffu, k8[q], 1);
#pragma unroll
        for (int q = 0; q < 8; ++q) ins8_32(t8[q], k8);
        if (half == 0) {
#pragma unroll
            for (int q = 0; q < 8; ++q)
                g_cand[(size_t)gi * CAND + bj * NCAND + q] = k8[q];
        }
    }
#undef LOAD_STAGE
}

// ---------------- merge + exact fp32 rescore -> final 5-NN -------------------
// warp per row; 1024 blocks x 256 threads
__global__ void __launch_bounds__(256) k_nn() {
    const int warp = threadIdx.x >> 5, lane = threadIdx.x & 31;
    const int r = blockIdx.x * 8 + warp;

    uint32_t k8[8] = {0,0,0,0,0,0,0,0};
    const size_t base = (size_t)r * CAND;
#pragma unroll
    for (int k = 0; k < CAND / 32; ++k)
        ins8_32(g_cand[base + lane + 32 * k], k8);
#pragma unroll
    for (int off = 16; off > 0; off >>= 1) {
        uint32_t t8[8];
#pragma unroll
        for (int q = 0; q < 8; ++q) t8[q] = __shfl_xor_sync(0xffffffffu, k8[q], off);
#pragma unroll
        for (int q = 0; q < 8; ++q) ins8_32(t8[q], k8);
    }

    // exact fp32 rescore of the 8 finalists
    float fr[8];
#pragma unroll
    for (int k = 0; k < 8; ++k) fr[k] = g_F[(size_t)r * D + lane + 32 * k];
    int   cidx[NCAND];
    float dots[NCAND];
#pragma unroll
    for (int q = 0; q < NCAND; ++q) {
        cidx[q] = keyIdx32(k8[q]);
        const float* fc = g_F + (size_t)cidx[q] * D;
        float s = 0.f;
#pragma unroll
        for (int k = 0; k < 8; ++k) s = fmaf(fr[k], fc[lane + 32 * k], s);
#pragma unroll
        for (int o = 16; o > 0; o >>= 1) s += __shfl_xor_sync(0xffffffffu, s, o);
        dots[q] = s;
    }
    float b5[KNN5]; int i5[KNN5];
#pragma unroll
    for (int q = 0; q < KNN5; ++q) { b5[q] = -__int_as_float(0x7f800000); i5[q] = 0x7fffffff; }
#pragma unroll
    for (int q = 0; q < NCAND; ++q) topk_insert<KNN5>(dots[q], cidx[q], b5, i5);
    if (lane < KNN5) g_nbr[r * KNN5 + lane] = (i5[lane] >= 0 && i5[lane] < N) ? i5[lane] : 0;
}

// ---------------- persistent mean-field iteration (flag-based global sync) ---
__global__ void __launch_bounds__(IT_THREADS) k_iterate(float* __restrict__ dout) {
    __shared__ float sE[IT_WARPS];
    __shared__ float sEarr[NB_IT];
    __shared__ float sEbc;
    const int tid  = threadIdx.x;
    const int lane = tid & 31, wib = tid >> 5;
    const int warpG = blockIdx.x * IT_WARPS + wib;
    const int nW = NB_IT * IT_WARPS;

    int nr = 0, rows[ROWS_MAX];
    float u0[ROWS_MAX], u1[ROWS_MAX];
    int   nb[ROWS_MAX][KNN5];
#pragma unroll
    for (int k = 0; k < ROWS_MAX; ++k) {
        rows[k] = 0; u0[k] = 0.f; u1[k] = 0.f;
#pragma unroll
        for (int n = 0; n < KNN5; ++n) nb[k][n] = 0;
    }
    for (int rr = warpG; rr < N; rr += nW) rows[nr++] = rr;
    for (int k = 0; k < nr; ++k) {
        u0[k] = g_unary[rows[k] * NC + lane];
        u1[k] = g_unary[rows[k] * NC + 32 + lane];
#pragma unroll
        for (int n = 0; n < KNN5; ++n) nb[k][n] = g_nbr[rows[k] * KNN5 + n];
    }

    float Eprev = __int_as_float(0x7f800000);
    int finalBuf = -1;

    for (int it = 0; it < MAXIT; ++it) {
        const float* __restrict__ Yin  = g_Ybuf[it & 1];
        float* __restrict__ Yout = g_Ybuf[(it + 1) & 1];

        float pw0[ROWS_MAX], pw1[ROWS_MAX];
#pragma unroll
        for (int k = 0; k < ROWS_MAX; ++k) {
            float a0 = 0.f, a1 = 0.f;
#pragma unroll
            for (int n = 0; n < KNN5; ++n) {
                const float* yr = Yin + (size_t)nb[k][n] * NC;
                a0 += yr[lane];
                a1 += yr[lane + 32];
            }
            pw0[k] = a0; pw1[k] = a1;
        }
        float x0[ROWS_MAX], x1[ROWS_MAX], m[ROWS_MAX], ssum[ROWS_MAX];
        float e0[ROWS_MAX], e1[ROWS_MAX];
#pragma unroll
        for (int k = 0; k < ROWS_MAX; ++k) {
            x0[k] = pw0[k] - u0[k]; x1[k] = pw1[k] - u1[k];
            m[k] = fmaxf(x0[k], x1[k]);
        }
#pragma unroll
        for (int o = 16; o > 0; o >>= 1)
#pragma unroll
            for (int k = 0; k < ROWS_MAX; ++k)
                m[k] = fmaxf(m[k], __shfl_xor_sync(0xffffffffu, m[k], o));
#pragma unroll
        for (int k = 0; k < ROWS_MAX; ++k) {
            e0[k] = __expf(x0[k] - m[k]); e1[k] = __expf(x1[k] - m[k]);
            ssum[k] = e0[k] + e1[k];
        }
#pragma unroll
        for (int o = 16; o > 0; o >>= 1)
#pragma unroll
            for (int k = 0; k < ROWS_MAX; ++k)
                ssum[k] += __shfl_xor_sync(0xffffffffu, ssum[k], o);

        float myE = 0.f;
#pragma unroll
        for (int k = 0; k < ROWS_MAX; ++k) {
            if (k < nr) {
                float inv = 1.0f / ssum[k];
                float y0 = e0[k] * inv, y1 = e1[k] * inv;
                const int rr = rows[k];
                Yout[rr * NC + lane]      = y0;
                Yout[rr * NC + 32 + lane] = y1;
                float ls = __logf(ssum[k]);
                myE += y0 * (u0[k] - pw0[k] + (x0[k] - m[k] - ls))
                     + y1 * (u1[k] - pw1[k] + (x1[k] - m[k] - ls));
            }
        }
#pragma unroll
        for (int o = 16; o > 0; o >>= 1) myE += __shfl_xor_sync(0xffffffffu, myE, o);
        if (lane == 0) sE[wib] = myE;
        __syncthreads();
        if (tid == 0) {
            float e = 0.f;
#pragma unroll
            for (int w = 0; w < IT_WARPS; ++w) e += sE[w];
            st_rel64(&g_slotE[(size_t)it * NB_IT + blockIdx.x],
                     ((uint64_t)1 << 32) | (uint64_t)__float_as_uint(e));
        }
        if (blockIdx.x == 0) {
            if (tid < NB_IT) {
                uint64_t v;
                do { v = ld_acq64(&g_slotE[(size_t)it * NB_IT + tid]); } while (!(v >> 32));
                sEarr[tid] = __uint_as_float((uint32_t)v);
            }
            __syncthreads();
            if (wib == 0) {
                const float* pe = sEarr;
                float e = pe[lane] + pe[lane + 32] + pe[lane + 64] + pe[lane + 96];
                if (lane < NB_IT - 128) e += pe[lane + 128];
#pragma unroll
                for (int o = 16; o > 0; o >>= 1) e += __shfl_xor_sync(0xffffffffu, e, o);
                if (lane == 0) {
                    sEbc = e;
                    st_rel64(&g_bcastE[it], ((uint64_t)1 << 32) | (uint64_t)__float_as_uint(e));
                }
            }
            __syncthreads();
        } else {
            if (tid == 0) {
                uint64_t v;
                do { v = ld_acq64(&g_bcastE[it]); } while (!(v >> 32));
                sEbc = __uint_as_float((uint32_t)v);
            }
            __syncthreads();
        }
        float E = sEbc;
        bool conv = (it > 1) && (fabsf(E - Eprev) <= 1e-8f * fabsf(Eprev));
        Eprev = E;
        if (conv) { finalBuf = (it + 1) & 1; break; }
        __syncthreads();
    }
    if (finalBuf < 0) finalBuf = MAXIT & 1;
    const float* __restrict__ Yf = g_Ybuf[finalBuf];
    for (int k = 0; k < nr; ++k) {
        const int rr = rows[k];
        dout[rr * NC + lane]      = Yf[rr * NC + lane];
        dout[rr * NC + 32 + lane] = Yf[rr * NC + 32 + lane];
    }
}

// ---------------- launch -----------------------------------------------------
extern "C" void kernel_launch(void* const* d_in, const int* in_sizes, int n_in,
                              void* d_out, int out_size) {
    const float* scores;
    const float* feats;
    if (in_sizes[0] == N * NC) { scores = (const float*)d_in[0]; feats = (const float*)d_in[1]; }
    else                       { scores = (const float*)d_in[1]; feats = (const float*)d_in[0]; }
    float* out = (float*)d_out;

    const int gram_smem = 98304;   // 96 KB (stages) / 128x132 f32 epilogue overlay
    cudaFuncSetAttribute(k_gram_mma, cudaFuncAttributeMaxDynamicSharedMemorySize, gram_smem);

    k_prep_unary<<<N / 8, 256>>>(scores);
    k_prep_feats<<<N, 256>>>(feats);
    k_gram_mma<<<NBI * (NBI + 1) / 2, 256, gram_smem>>>();
    k_nn<<<N / 8, 256>>>();
    k_iterate<<<NB_IT, IT_THREADS>>>(out);
}

// round 12
// speedup vs baseline: 5.4109x; 1.1395x over previous
#include <cuda_runtime.h>
#include <cuda_bf16.h>
#include <math.h>
#include <stdint.h>

#define N      8192
#define D      256
#define NC     64
#define KNN5   5
#define TI     128
#define KC     64           // bf16 per smem stage (128 B/row)
#define NSTG   4            // K=256 / 64
#define NBI    (N/TI)       // 64 block-rows
#define NCAND  5            // approx candidates kept per tile
#define CAND   (NBI*NCAND)  // 320 candidate slots per row
#define NFIN   8            // finalists rescored exactly
#define CSTRIDE 132         // float4-aligned epilogue stride
#define NB_IT  148
#define IT_THREADS 512
#define IT_WARPS   16
#define ROWS_MAX   4
#define MAXIT  100
#define LAM    1.0f

// ---------------- scratch ----------------------------------------------------
__device__ __nv_bfloat16 g_H[(size_t)N * D];    // bf16(normalized feats)
__device__ float g_F[(size_t)N * D];            // fp32 normalized feats
__device__ float g_unary[N * NC];
__device__ float g_Ybuf[2][N * NC];
__device__ uint32_t g_cand[(size_t)N * CAND];   // packed {val:19 | (8191-idx):13}
__device__ int   g_nbr[N * KNN5];
__device__ uint64_t g_slotE[(size_t)MAXIT * NB_IT];
__device__ uint64_t g_bcastE[MAXIT];

// ---------------- PTX helpers ------------------------------------------------
__device__ __forceinline__ uint32_t smem_u32(const void* p) {
    uint32_t a;
    asm("{ .reg .u64 t; cvta.to.shared.u64 t, %1; cvt.u32.u64 %0, t; }" : "=r"(a) : "l"(p));
    return a;
}
#define SWZ128(o) ((o) ^ (((o) >> 3) & 0x70))
#define CP_ASYNC16(dst, src) \
    asm volatile("cp.async.cg.shared.global [%0], [%1], 16;" :: "r"(dst), "l"(src) : "memory")
#define CP_COMMIT() asm volatile("cp.async.commit_group;" ::: "memory")
#define CP_WAIT(n)  asm volatile("cp.async.wait_group %0;" :: "n"(n) : "memory")
#define LDSM_X4(r0,r1,r2,r3, a) \
    asm volatile("ldmatrix.sync.aligned.m8n8.x4.shared.b16 {%0,%1,%2,%3}, [%4];" \
        : "=r"(r0),"=r"(r1),"=r"(r2),"=r"(r3) : "r"(a))
#define LDSM_X2(r0,r1, a) \
    asm volatile("ldmatrix.sync.aligned.m8n8.x2.shared.b16 {%0,%1}, [%2];" \
        : "=r"(r0),"=r"(r1) : "r"(a))
#define MMA16816(d, a, b) \
    asm volatile("mma.sync.aligned.m16n8k16.row.col.f32.bf16.bf16.f32 " \
        "{%0,%1,%2,%3}, {%4,%5,%6,%7}, {%8,%9}, {%0,%1,%2,%3};" \
        : "+f"((d)[0]),"+f"((d)[1]),"+f"((d)[2]),"+f"((d)[3]) \
        : "r"((a)[0]),"r"((a)[1]),"r"((a)[2]),"r"((a)[3]), "r"((b)[0]),"r"((b)[1]))

__device__ __forceinline__ void st_rel64(uint64_t* p, uint64_t v) {
    asm volatile("st.release.gpu.global.b64 [%0], %1;" :: "l"(p), "l"(v) : "memory");
}
__device__ __forceinline__ uint64_t ld_acq64(const uint64_t* p) {
    uint64_t v;
    asm volatile("ld.acquire.gpu.global.b64 %0, [%1];" : "=l"(v) : "l"(p) : "memory");
    return v;
}

// ---------------- packed u32 keys: {orderable_val:19 | (8191-idx):13} --------
__device__ __forceinline__ uint32_t packKey32(float v, int idx) {
    uint32_t b = __float_as_uint(v);
    b = (b & 0x80000000u) ? ~b : (b | 0x80000000u);   // order-preserving
    return (b & 0xFFFFE000u) | (uint32_t)(8191 - idx);
}
__device__ __forceinline__ int keyIdx32(uint32_t k) { return 8191 - (int)(k & 0x1FFFu); }
__device__ __forceinline__ float unpackLB32(uint32_t k) {   // bin lower bound
    uint32_t m = k & 0xFFFFE000u;
    uint32_t o = (m & 0x80000000u) ? (m & 0x7FFFFFFFu) : ~m;
    return __uint_as_float(o);
}
__device__ __forceinline__ void ins5_32(uint32_t k, uint32_t* a) {
    if (k > a[4]) {
        a[4] = k;
#pragma unroll
        for (int s = 4; s > 0; --s) {
            uint32_t hi = max(a[s], a[s-1]), lo = min(a[s], a[s-1]);
            a[s-1] = hi; a[s] = lo;
        }
    }
}
__device__ __forceinline__ void ins8_32(uint32_t k, uint32_t* a) {
    if (k > a[7]) {
        a[7] = k;
#pragma unroll
        for (int s = 7; s > 0; --s) {
            uint32_t hi = max(a[s], a[s-1]), lo = min(a[s], a[s-1]);
            a[s-1] = hi; a[s] = lo;
        }
    }
}
template <int K>
__device__ __forceinline__ void topk_insert(float v, int j, float* bv, int* bi) {
    if (v > bv[K-1] || (v == bv[K-1] && j < bi[K-1])) {
        bv[K-1] = v; bi[K-1] = j;
#pragma unroll
        for (int s = K-1; s > 0; --s) {
            if (bv[s] > bv[s-1] || (bv[s] == bv[s-1] && bi[s] < bi[s-1])) {
                float tv = bv[s]; bv[s] = bv[s-1]; bv[s-1] = tv;
                int   tj = bi[s]; bi[s] = bi[s-1]; bi[s-1] = tj;
            }
        }
    }
}

// ---------------- prep: unary + Y0 (+ sync-slot reset, graph-replay safe) ----
__global__ void k_prep_unary(const float* __restrict__ scores) {
    int wib = threadIdx.x >> 5, lane = threadIdx.x & 31;
    int r = blockIdx.x * 8 + wib;
    int gidx = blockIdx.x * 256 + threadIdx.x;
    if (gidx < MAXIT * NB_IT) g_slotE[gidx] = 0ull;
    if (gidx < MAXIT) g_bcastE[gidx] = 0ull;

    const float* s = scores + (size_t)r * NC;
    float u0 = -logf(s[lane]      + 1e-10f);
    float u1 = -logf(s[lane + 32] + 1e-10f);
    g_unary[r * NC + lane]      = u0;
    g_unary[r * NC + 32 + lane] = u1;
    float x0 = -u0, x1 = -u1;
    float m = fmaxf(x0, x1);
#pragma unroll
    for (int o = 16; o > 0; o >>= 1) m = fmaxf(m, __shfl_xor_sync(0xffffffffu, m, o));
    float e0 = __expf(x0 - m), e1 = __expf(x1 - m);
    float t = e0 + e1;
#pragma unroll
    for (int o = 16; o > 0; o >>= 1) t += __shfl_xor_sync(0xffffffffu, t, o);
    float inv = 1.0f / t;
    g_Ybuf[0][r * NC + lane]      = e0 * inv;
    g_Ybuf[0][r * NC + 32 + lane] = e1 * inv;
}

// ---------------- prep: normalize -> fp32 + bf16 -----------------------------
__global__ void k_prep_feats(const float* __restrict__ feats) {
    __shared__ float red[8];
    __shared__ float nrmsh;
    int r = blockIdx.x, k = threadIdx.x;
    int lane = k & 31, w = k >> 5;
    float v = feats[(size_t)r * D + k];
    float s = v * v;
#pragma unroll
    for (int o = 16; o > 0; o >>= 1) s += __shfl_xor_sync(0xffffffffu, s, o);
    if (lane == 0) red[w] = s;
    __syncthreads();
    if (k == 0) {
        float t = 0.f;
#pragma unroll
        for (int i = 0; i < 8; ++i) t += red[i];
        nrmsh = sqrtf(t);
    }
    __syncthreads();
    float f = v / fmaxf(nrmsh, 1e-12f);
    g_F[(size_t)r * D + k] = f;
    g_H[(size_t)r * D + k] = __float2bfloat16(f);
}

// ---------------- bf16 Gram (K=256), upper-triangle, top-5 per tile ----------
// grid 2080 x 256; dynamic smem = 98304 B (3x32KB stages; 128x132 f32 epilogue)
__global__ void __launch_bounds__(256, 2) k_gram_mma() {
    extern __shared__ char smem[];
    float* Cs = (float*)smem;
    const uint32_t sb = smem_u32(smem);
    const int tid = threadIdx.x;
    const int lane = tid & 31, warp = tid >> 5;
    const int wm = warp >> 2, wn = warp & 3;

    int bi = 0, rem = blockIdx.x;
    while (rem >= NBI - bi) { rem -= NBI - bi; ++bi; }
    const int bj = bi + rem;
    const int ib = bi * TI, jb = bj * TI;

    float acc[4][4][4];
#pragma unroll
    for (int mf = 0; mf < 4; ++mf)
#pragma unroll
        for (int nf = 0; nf < 4; ++nf)
#pragma unroll
            for (int q = 0; q < 4; ++q) acc[mf][nf][q] = 0.f;

    const char* gH = (const char*)g_H;

#define LOAD_STAGE(sidx) do {                                                   \
        int _s = (sidx); uint32_t _b = (uint32_t)((sidx) % 3) * 32768u;         \
        _Pragma("unroll")                                                       \
        for (int t = 0; t < 4; ++t) {                                           \
            int e = tid + t * 256;                                              \
            int row = e >> 3, ch = e & 7;                                       \
            uint32_t off = SWZ128((uint32_t)(row * 128 + ch * 16));             \
            CP_ASYNC16(sb + _b + off,                                           \
                gH + ((size_t)(ib + row) * D + (size_t)_s * KC) * 2 + ch * 16); \
            CP_ASYNC16(sb + _b + 16384u + off,                                  \
                gH + ((size_t)(jb + row) * D + (size_t)_s * KC) * 2 + ch * 16); \
        }                                                                       \
        CP_COMMIT();                                                            \
    } while (0)

    LOAD_STAGE(0);
    LOAD_STAGE(1);

    for (int s = 0; s < NSTG; ++s) {
        if (s == NSTG - 1) { CP_WAIT(0); } else { CP_WAIT(1); }
        __syncthreads();
        if (s + 2 < NSTG) LOAD_STAGE(s + 2);

        const uint32_t aS = sb + (uint32_t)(s % 3) * 32768u;
        const uint32_t bS = aS + 16384u;
#pragma unroll
        for (int kk = 0; kk < 4; ++kk) {
            uint32_t a[4][4], b[4][2];
#pragma unroll
            for (int mf = 0; mf < 4; ++mf) {
                int row = wm * 64 + mf * 16 + (lane & 15);
                uint32_t kb = kk * 32 + ((lane >> 4) << 4);
                LDSM_X4(a[mf][0], a[mf][1], a[mf][2], a[mf][3], aS + SWZ128((uint32_t)(row * 128) + kb));
            }
#pragma unroll
            for (int nf = 0; nf < 4; ++nf) {
                int nrow = wn * 32 + nf * 8 + (lane & 7);
                uint32_t kb = kk * 32 + (((lane >> 3) & 1) << 4);
                LDSM_X2(b[nf][0], b[nf][1], bS + SWZ128((uint32_t)(nrow * 128) + kb));
            }
#pragma unroll
            for (int mf = 0; mf < 4; ++mf)
#pragma unroll
                for (int nf = 0; nf < 4; ++nf)
                    MMA16816(acc[mf][nf], a[mf], b[nf]);
        }
    }

    // dump ALL fragments -> smem (accumulators die)
    __syncthreads();
#pragma unroll
    for (int mf = 0; mf < 4; ++mf)
#pragma unroll
        for (int nf = 0; nf < 4; ++nf) {
            int r0 = wm * 64 + mf * 16 + (lane >> 2);
            int c0 = wn * 32 + nf * 8 + 2 * (lane & 3);
            Cs[r0 * CSTRIDE + c0]           = acc[mf][nf][0];
            Cs[r0 * CSTRIDE + c0 + 1]       = acc[mf][nf][1];
            Cs[(r0 + 8) * CSTRIDE + c0]     = acc[mf][nf][2];
            Cs[(r0 + 8) * CSTRIDE + c0 + 1] = acc[mf][nf][3];
        }
    __syncthreads();

    if (bi != bj) {
        // off-diagonal: interleaved i-side (rows) + j-side (cols) scans.
        const int row = tid >> 1, half = tid & 1;
        const int gi = ib + row;
        const int gj = jb + row;
        uint32_t k5i[5] = {0,0,0,0,0};
        uint32_t k5j[5] = {0,0,0,0,0};
        float thi = -3.0e38f, thj = -3.0e38f;
        const float* rowp = Cs + row * CSTRIDE + half * 64;
        const float* colp = Cs + (half * 64) * CSTRIDE + row;
        const int cbase0 = jb + half * 64;
        const int rbase0 = ib + half * 64;
#pragma unroll 4
        for (int c4 = 0; c4 < 16; ++c4) {
            float4 v = *(const float4*)(rowp + c4 * 4);
            float w0 = colp[(c4 * 4 + 0) * CSTRIDE];
            float w1 = colp[(c4 * 4 + 1) * CSTRIDE];
            float w2 = colp[(c4 * 4 + 2) * CSTRIDE];
            float w3 = colp[(c4 * 4 + 3) * CSTRIDE];
            float bmi = fmaxf(fmaxf(v.x, v.y), fmaxf(v.z, v.w));
            float bmj = fmaxf(fmaxf(w0, w1), fmaxf(w2, w3));
            if (bmi > thi) {
                int cb = cbase0 + c4 * 4;
                if (v.x > thi) ins5_32(packKey32(v.x, cb + 0), k5i);
                if (v.y > thi) ins5_32(packKey32(v.y, cb + 1), k5i);
                if (v.z > thi) ins5_32(packKey32(v.z, cb + 2), k5i);
                if (v.w > thi) ins5_32(packKey32(v.w, cb + 3), k5i);
                thi = k5i[4] ? unpackLB32(k5i[4]) : -3.0e38f;
            }
            if (bmj > thj) {
                int rb = rbase0 + c4 * 4;
                if (w0 > thj) ins5_32(packKey32(w0, rb + 0), k5j);
                if (w1 > thj) ins5_32(packKey32(w1, rb + 1), k5j);
                if (w2 > thj) ins5_32(packKey32(w2, rb + 2), k5j);
                if (w3 > thj) ins5_32(packKey32(w3, rb + 3), k5j);
                thj = k5j[4] ? unpackLB32(k5j[4]) : -3.0e38f;
            }
        }
        uint32_t t5[5];
#pragma unroll
        for (int q = 0; q < 5; ++q) t5[q] = __shfl_xor_sync(0xffffffffu, k5i[q], 1);
#pragma unroll
        for (int q = 0; q < 5; ++q) ins5_32(t5[q], k5i);
#pragma unroll
        for (int q = 0; q < 5; ++q) t5[q] = __shfl_xor_sync(0xffffffffu, k5j[q], 1);
#pragma unroll
        for (int q = 0; q < 5; ++q) ins5_32(t5[q], k5j);
        if (half == 0) {
#pragma unroll
            for (int q = 0; q < 5; ++q) {
                g_cand[(size_t)gi * CAND + bj * NCAND + q] = k5i[q];
                g_cand[(size_t)gj * CAND + bi * NCAND + q] = k5j[q];
            }
        }
    } else {
        // diagonal: i-side only, with self-exclusion
        const int row = tid >> 1, half = tid & 1;
        const int gi = ib + row;
        uint32_t k5[5] = {0,0,0,0,0};
        float th = -3.0e38f;
        const float* rowp = Cs + row * CSTRIDE + half * 64;
        const int cbase0 = jb + half * 64;
#pragma unroll 4
        for (int c4 = 0; c4 < 16; ++c4) {
            float4 v = *(const float4*)(rowp + c4 * 4);
            float bm = fmaxf(fmaxf(v.x, v.y), fmaxf(v.z, v.w));
            if (bm > th) {
                int cb = cbase0 + c4 * 4;
                if (cb + 0 != gi && v.x > th) ins5_32(packKey32(v.x, cb + 0), k5);
                if (cb + 1 != gi && v.y > th) ins5_32(packKey32(v.y, cb + 1), k5);
                if (cb + 2 != gi && v.z > th) ins5_32(packKey32(v.z, cb + 2), k5);
                if (cb + 3 != gi && v.w > th) ins5_32(packKey32(v.w, cb + 3), k5);
                th = k5[4] ? unpackLB32(k5[4]) : -3.0e38f;
            }
        }
        uint32_t t5[5];
#pragma unroll
        for (int q = 0; q < 5; ++q) t5[q] = __shfl_xor_sync(0xffffffffu, k5[q], 1);
#pragma unroll
        for (int q = 0; q < 5; ++q) ins5_32(t5[q], k5);
        if (half == 0) {
#pragma unroll
            for (int q = 0; q < 5; ++q)
                g_cand[(size_t)gi * CAND + bj * NCAND + q] = k5[q];
        }
    }
#undef LOAD_STAGE
}

// ---------------- merge + exact fp32 rescore -> final 5-NN -------------------
// warp per row; 1024 blocks x 256 threads
__global__ void __launch_bounds__(256) k_nn() {
    const int warp = threadIdx.x >> 5, lane = threadIdx.x & 31;
    const int r = blockIdx.x * 8 + warp;

    uint32_t k8[8] = {0,0,0,0,0,0,0,0};
    const size_t base = (size_t)r * CAND;
#pragma unroll
    for (int k = 0; k < CAND / 32; ++k)
        ins8_32(g_cand[base + lane + 32 * k], k8);
#pragma unroll
    for (int off = 16; off > 0; off >>= 1) {
        uint32_t t8[8];
#pragma unroll
        for (int q = 0; q < 8; ++q) t8[q] = __shfl_xor_sync(0xffffffffu, k8[q], off);
#pragma unroll
        for (int q = 0; q < 8; ++q) ins8_32(t8[q], k8);
    }

    // exact fp32 rescore of the 8 finalists
    float fr[8];
#pragma unroll
    for (int k = 0; k < 8; ++k) fr[k] = g_F[(size_t)r * D + lane + 32 * k];
    int   cidx[NFIN];
    float dots[NFIN];
#pragma unroll
    for (int q = 0; q < NFIN; ++q) {
        cidx[q] = keyIdx32(k8[q]);
        const float* fc = g_F + (size_t)cidx[q] * D;
        float s = 0.f;
#pragma unroll
        for (int k = 0; k < 8; ++k) s = fmaf(fr[k], fc[lane + 32 * k], s);
#pragma unroll
        for (int o = 16; o > 0; o >>= 1) s += __shfl_xor_sync(0xffffffffu, s, o);
        dots[q] = s;
    }
    float b5[KNN5]; int i5[KNN5];
#pragma unroll
    for (int q = 0; q < KNN5; ++q) { b5[q] = -__int_as_float(0x7f800000); i5[q] = 0x7fffffff; }
#pragma unroll
    for (int q = 0; q < NFIN; ++q) topk_insert<KNN5>(dots[q], cidx[q], b5, i5);
    if (lane < KNN5) g_nbr[r * KNN5 + lane] = (i5[lane] >= 0 && i5[lane] < N) ? i5[lane] : 0;
}

// ---------------- persistent mean-field iteration (flag-based global sync) ---
__global__ void __launch_bounds__(IT_THREADS) k_iterate(float* __restrict__ dout) {
    __shared__ float sE[IT_WARPS];
    __shared__ float sEarr[NB_IT];
    __shared__ float sEbc;
    const int tid  = threadIdx.x;
    const int lane = tid & 31, wib = tid >> 5;
    const int warpG = blockIdx.x * IT_WARPS + wib;
    const int nW = NB_IT * IT_WARPS;

    int nr = 0, rows[ROWS_MAX];
    float u0[ROWS_MAX], u1[ROWS_MAX];
    int   nb[ROWS_MAX][KNN5];
#pragma unroll
    for (int k = 0; k < ROWS_MAX; ++k) {
        rows[k] = 0; u0[k] = 0.f; u1[k] = 0.f;
#pragma unroll
        for (int n = 0; n < KNN5; ++n) nb[k][n] = 0;
    }
    for (int rr = warpG; rr < N; rr += nW) rows[nr++] = rr;
    for (int k = 0; k < nr; ++k) {
        u0[k] = g_unary[rows[k] * NC + lane];
        u1[k] = g_unary[rows[k] * NC + 32 + lane];
#pragma unroll
        for (int n = 0; n < KNN5; ++n) nb[k][n] = g_nbr[rows[k] * KNN5 + n];
    }

    float Eprev = __int_as_float(0x7f800000);
    int finalBuf = -1;

    for (int it = 0; it < MAXIT; ++it) {
        const float* __restrict__ Yin  = g_Ybuf[it & 1];
        float* __restrict__ Yout = g_Ybuf[(it + 1) & 1];

        float pw0[ROWS_MAX], pw1[ROWS_MAX];
#pragma unroll
        for (int k = 0; k < ROWS_MAX; ++k) {
            float a0 = 0.f, a1 = 0.f;
#pragma unroll
            for (int n = 0; n < KNN5; ++n) {
                const float* yr = Yin + (size_t)nb[k][n] * NC;
                a0 += yr[lane];
                a1 += yr[lane + 32];
            }
            pw0[k] = a0; pw1[k] = a1;
        }
        float x0[ROWS_MAX], x1[ROWS_MAX], m[ROWS_MAX], ssum[ROWS_MAX];
        float e0[ROWS_MAX], e1[ROWS_MAX];
#pragma unroll
        for (int k = 0; k < ROWS_MAX; ++k) {
            x0[k] = pw0[k] - u0[k]; x1[k] = pw1[k] - u1[k];
            m[k] = fmaxf(x0[k], x1[k]);
        }
#pragma unroll
        for (int o = 16; o > 0; o >>= 1)
#pragma unroll
            for (int k = 0; k < ROWS_MAX; ++k)
                m[k] = fmaxf(m[k], __shfl_xor_sync(0xffffffffu, m[k], o));
#pragma unroll
        for (int k = 0; k < ROWS_MAX; ++k) {
            e0[k] = __expf(x0[k] - m[k]); e1[k] = __expf(x1[k] - m[k]);
            ssum[k] = e0[k] + e1[k];
        }
#pragma unroll
        for (int o = 16; o > 0; o >>= 1)
#pragma unroll
            for (int k = 0; k < ROWS_MAX; ++k)
                ssum[k] += __shfl_xor_sync(0xffffffffu, ssum[k], o);

        float myE = 0.f;
#pragma unroll
        for (int k = 0; k < ROWS_MAX; ++k) {
            if (k < nr) {
                float inv = 1.0f / ssum[k];
                float y0 = e0[k] * inv, y1 = e1[k] * inv;
                const int rr = rows[k];
                Yout[rr * NC + lane]      = y0;
                Yout[rr * NC + 32 + lane] = y1;
                float ls = __logf(ssum[k]);
                myE += y0 * (u0[k] - pw0[k] + (x0[k] - m[k] - ls))
                     + y1 * (u1[k] - pw1[k] + (x1[k] - m[k] - ls));
            }
        }
#pragma unroll
        for (int o = 16; o > 0; o >>= 1) myE += __shfl_xor_sync(0xffffffffu, myE, o);
        if (lane == 0) sE[wib] = myE;
        __syncthreads();
        if (tid == 0) {
            float e = 0.f;
#pragma unroll
            for (int w = 0; w < IT_WARPS; ++w) e += sE[w];
            st_rel64(&g_slotE[(size_t)it * NB_IT + blockIdx.x],
                     ((uint64_t)1 << 32) | (uint64_t)__float_as_uint(e));
        }
        if (blockIdx.x == 0) {
            if (tid < NB_IT) {
                uint64_t v;
                do { v = ld_acq64(&g_slotE[(size_t)it * NB_IT + tid]); } while (!(v >> 32));
                sEarr[tid] = __uint_as_float((uint32_t)v);
            }
            __syncthreads();
            if (wib == 0) {
                const float* pe = sEarr;
                float e = pe[lane] + pe[lane + 32] + pe[lane + 64] + pe[lane + 96];
                if (lane < NB_IT - 128) e += pe[lane + 128];
#pragma unroll
                for (int o = 16; o > 0; o >>= 1) e += __shfl_xor_sync(0xffffffffu, e, o);
                if (lane == 0) {
                    sEbc = e;
                    st_rel64(&g_bcastE[it], ((uint64_t)1 << 32) | (uint64_t)__float_as_uint(e));
                }
            }
            __syncthreads();
        } else {
            if (tid == 0) {
                uint64_t v;
                do { v = ld_acq64(&g_bcastE[it]); } while (!(v >> 32));
                sEbc = __uint_as_float((uint32_t)v);
            }
            __syncthreads();
        }
        float E = sEbc;
        bool conv = (it > 1) && (fabsf(E - Eprev) <= 1e-8f * fabsf(Eprev));
        Eprev = E;
        if (conv) { finalBuf = (it + 1) & 1; break; }
        __syncthreads();
    }
    if (finalBuf < 0) finalBuf = MAXIT & 1;
    const float* __restrict__ Yf = g_Ybuf[finalBuf];
    for (int k = 0; k < nr; ++k) {
        const int rr = rows[k];
        dout[rr * NC + lane]      = Yf[rr * NC + lane];
        dout[rr * NC + 32 + lane] = Yf[rr * NC + 32 + lane];
    }
}

// ---------------- launch -----------------------------------------------------
extern "C" void kernel_launch(void* const* d_in, const int* in_sizes, int n_in,
                              void* d_out, int out_size) {
    const float* scores;
    const float* feats;
    if (in_sizes[0] == N * NC) { scores = (const float*)d_in[0]; feats = (const float*)d_in[1]; }
    else                       { scores = (const float*)d_in[1]; feats = (const float*)d_in[0]; }
    float* out = (float*)d_out;

    const int gram_smem = 98304;   // 96 KB (stages) / 128x132 f32 epilogue overlay
    cudaFuncSetAttribute(k_gram_mma, cudaFuncAttributeMaxDynamicSharedMemorySize, gram_smem);

    k_prep_unary<<<N / 8, 256>>>(scores);
    k_prep_feats<<<N, 256>>>(feats);
    k_gram_mma<<<NBI * (NBI + 1) / 2, 256, gram_smem>>>();
    k_nn<<<N / 8, 256>>>();
    k_iterate<<<NB_IT, IT_THREADS>>>(out);
}